// round 7
// baseline (speedup 1.0000x reference)
#include <cuda_runtime.h>
#include <cuda_fp16.h>
#include <math.h>
#include <stdint.h>

#define BB 8
#define LL 2048
#define WW 1024
#define KK 5
#define GG 2
#define CI 512
#define CO 512
#define RDIM (KK*CI)        // 2560

// GEMM tiling
#define MT   128            // M per CTA
#define NTT  256            // N per CTA
#define KCB  32             // K-chunk (fp16 elems, 64B rows)
#define NCH  (RDIM/KCB)     // 80 chunks

// ---- static scratch ----
__device__ __half g_Bh[GG*CO*RDIM];           // [g][o][r] K-major, fp16
__device__ int   g_p0[BB*LL*KK];
__device__ float g_frac[BB*LL*KK];
__device__ float g_h[(size_t)BB*LL*WW];       // conv output, 64 MB
__device__ float g_s[BB*LL];

// ============================================================
__device__ __forceinline__ uint32_t smem_u32(const void* p) {
    uint32_t a;
    asm("{ .reg .u64 t; cvta.to.shared.u64 t, %1; cvt.u32.u64 %0, t; }" : "=r"(a) : "l"(p));
    return a;
}
#define LDSM4(r, addr) \
    asm volatile("ldmatrix.sync.aligned.m8n8.x4.shared.b16 {%0,%1,%2,%3}, [%4];" \
        : "=r"((r)[0]), "=r"((r)[1]), "=r"((r)[2]), "=r"((r)[3]) : "r"(addr))
#define MMA16816(d, a, b0, b1) \
    asm volatile("mma.sync.aligned.m16n8k16.row.col.f32.f16.f16.f32 " \
        "{%0,%1,%2,%3}, {%4,%5,%6,%7}, {%8,%9}, {%0,%1,%2,%3};" \
        : "+f"((d)[0]), "+f"((d)[1]), "+f"((d)[2]), "+f"((d)[3]) \
        : "r"((a)[0]), "r"((a)[1]), "r"((a)[2]), "r"((a)[3]), "r"(b0), "r"(b1))

// ============================================================
// Kernel 1: B prep — conv_w [g][o][c][k] -> fp16 [g][o][r=k*CI+c]
// ============================================================
__global__ void prep_b_kernel(const float* __restrict__ conv_w) {
    int idx = blockIdx.x * 256 + threadIdx.x;
    if (idx >= GG*CO*RDIM) return;
    int r = idx % RDIM;
    int o = (idx / RDIM) % CO;
    int g = idx / (RDIM*CO);
    int k = r / CI, c = r % CI;
    float w = conv_w[(((g*CO + o)*CI + c)*KK) + k];
    g_Bh[idx] = __float2half_rn(w);
}

// ============================================================
// Kernel 2: offsets
// ============================================================
__global__ void offsets_kernel(const float* __restrict__ x,
                               const float* __restrict__ w_off,
                               const float* __restrict__ b_off) {
    int row = blockIdx.x;
    int tid = threadIdx.x;                // 128
    const float* xr = x + (size_t)row * WW;
    float acc[KK] = {0.f, 0.f, 0.f, 0.f, 0.f};
    for (int w = tid; w < WW; w += 128) {
        float xv = xr[w];
        #pragma unroll
        for (int k = 0; k < KK; k++) acc[k] += xv * w_off[w*KK + k];
    }
    __shared__ float sh[KK][128];
    #pragma unroll
    for (int k = 0; k < KK; k++) sh[k][tid] = acc[k];
    __syncthreads();
    for (int s = 64; s > 0; s >>= 1) {
        if (tid < s) {
            #pragma unroll
            for (int k = 0; k < KK; k++) sh[k][tid] += sh[k][tid + s];
        }
        __syncthreads();
    }
    if (tid < KK) {
        int k = tid;
        float off = tanhf(sh[k][0] + b_off[k]) * 2.0f;
        int l = row & (LL - 1);
        float pos = (float)l + ((float)k - 2.0f) + off;
        float p0 = floorf(pos);
        g_p0[row*KK + k]   = (int)p0;
        g_frac[row*KK + k] = pos - p0;
    }
}

// ============================================================
// Kernel 3: 2-term split-fp16 HMMA gathered GEMM
// grid (GG*2, 128); 512 threads = 16 warps (4m x 4n), warp tile 32x64
// SMEM stage (32KB): A_hi 8K | A_lo 8K | B 16K; 2 stages
// rows are 64B (32 fp16); swizzle: grp16 ^= (row>>1)&3
// ============================================================
#define SA_HI(s) ((s)*32768 + 0)
#define SA_LO(s) ((s)*32768 + 8192)
#define SB(s)    ((s)*32768 + 16384)
#define SMEM_CONV (2*32768)

__global__ void __launch_bounds__(512, 2) conv_mma_kernel(const float* __restrict__ x) {
    extern __shared__ __align__(128) char smem[];
    const uint32_t sb = smem_u32(smem);

    const int tid  = threadIdx.x;
    const int lane = tid & 31;
    const int wid  = tid >> 5;

    const int g      = blockIdx.x >> 1;
    const int n_base = (blockIdx.x & 1) * NTT;
    const int m_base = blockIdx.y * MT;

    // ---- A loader mapping: thread t -> (row = t>>2, 8-col group = t&3) ----
    const int lrow = tid >> 2;
    const int lgrp = tid & 3;
    const int mg   = m_base + lrow;
    const float* xb = x + ((size_t)(mg >> 11)) * LL * WW + g * CI + lgrp * 8;
    const int*   p0p = &g_p0[mg * KK];
    const float* frp = &g_frac[mg * KK];
    const uint32_t offSTA = (uint32_t)(lrow * 64 + ((lgrp ^ ((lrow >> 1) & 3)) << 4));

    // ---- B loader mapping: thread t -> (row = t>>1, 32B half = t&1) ----
    const int brow = tid >> 1;
    const int bhalf = tid & 1;
    const size_t gBrow = (size_t)(g * CO + n_base + brow) * RDIM + bhalf * 16;
    const uint32_t offSTB0 = (uint32_t)(brow * 64 + (((bhalf*2 + 0) ^ ((brow >> 1) & 3)) << 4));
    const uint32_t offSTB1 = (uint32_t)(brow * 64 + (((bhalf*2 + 1) ^ ((brow >> 1) & 3)) << 4));

    // ---- compute mapping ----
    const int wm = (wid & 3) * 32;       // warp m offset
    const int wn = (wid >> 2) * 64;      // warp n offset
    const int rA0 = wm + (lane & 15), rA1 = rA0 + 16;
    const int sA0 = (rA0 >> 1) & 3, sA1 = (rA1 >> 1) & 3;
    const int hi16 = lane >> 4;

    float acc[2][8][4];
    #pragma unroll
    for (int mi = 0; mi < 2; mi++)
        #pragma unroll
        for (int nb = 0; nb < 8; nb++)
            #pragma unroll
            for (int e = 0; e < 4; e++) acc[mi][nb][e] = 0.f;

    // staging registers
    float4 a00, a01, a10, a11;
    uint4 bv0, bv1;
    float lfrac;

    auto LOADG = [&](int ch) {
        int ktap = ch >> 4;
        int c0   = (ch & 15) * KCB;
        int p0   = p0p[ktap];
        lfrac    = frp[ktap];
        int ok0 = (p0 >= 0) & (p0 < LL);
        int ok1 = (p0 >= -1) & (p0 < LL - 1);
        const float* pa = xb + c0 + (size_t)p0 * WW;
        float4 z = make_float4(0.f, 0.f, 0.f, 0.f);
        a00 = z; a01 = z; a10 = z; a11 = z;
        if (ok0) { a00 = *(const float4*)(pa);      a01 = *(const float4*)(pa + 4); }
        if (ok1) { a10 = *(const float4*)(pa + WW); a11 = *(const float4*)(pa + WW + 4); }
        const __half* pb = g_Bh + gBrow + ch * KCB;
        bv0 = *(const uint4*)(pb);
        bv1 = *(const uint4*)(pb + 8);
    };

    auto STORES = [&](int s) {
        float w0 = 1.0f - lfrac, w1 = lfrac;
        float v[8];
        v[0] = a00.x*w0 + a10.x*w1; v[1] = a00.y*w0 + a10.y*w1;
        v[2] = a00.z*w0 + a10.z*w1; v[3] = a00.w*w0 + a10.w*w1;
        v[4] = a01.x*w0 + a11.x*w1; v[5] = a01.y*w0 + a11.y*w1;
        v[6] = a01.z*w0 + a11.z*w1; v[7] = a01.w*w0 + a11.w*w1;
        __half hv[8], lv[8];
        #pragma unroll
        for (int e = 0; e < 8; e++) {
            hv[e] = __float2half_rn(v[e]);
            lv[e] = __float2half_rn(v[e] - __half2float(hv[e]));
        }
        *(uint4*)(smem + SA_HI(s) + offSTA) = *(uint4*)hv;
        *(uint4*)(smem + SA_LO(s) + offSTA) = *(uint4*)lv;
        *(uint4*)(smem + SB(s) + offSTB0) = bv0;
        *(uint4*)(smem + SB(s) + offSTB1) = bv1;
    };

    auto COMPUTE = [&](int s) {
        const uint32_t bAhi = sb + SA_HI(s), bAlo = sb + SA_LO(s), bBs = sb + SB(s);
        #pragma unroll
        for (int ks = 0; ks < 2; ks++) {
            const int grp = ks * 2 + hi16;
            const uint32_t oA0 = (uint32_t)(rA0 * 64 + ((grp ^ sA0) << 4));
            const uint32_t oA1 = (uint32_t)(rA1 * 64 + ((grp ^ sA1) << 4));
            uint32_t ah0[4], ah1[4], al0[4], al1[4], bb[4][4];
            LDSM4(ah0, bAhi + oA0);  LDSM4(ah1, bAhi + oA1);
            LDSM4(al0, bAlo + oA0);  LDSM4(al1, bAlo + oA1);
            #pragma unroll
            for (int b4 = 0; b4 < 4; b4++) {
                int rB = wn + b4 * 16 + (lane & 15);
                uint32_t oB = (uint32_t)(rB * 64 + ((grp ^ ((rB >> 1) & 3)) << 4));
                LDSM4(bb[b4], bBs + oB);
            }
            #pragma unroll
            for (int b4 = 0; b4 < 4; b4++) {
                MMA16816(acc[0][b4*2],   ah0, bb[b4][0], bb[b4][2]);
                MMA16816(acc[0][b4*2+1], ah0, bb[b4][1], bb[b4][3]);
                MMA16816(acc[1][b4*2],   ah1, bb[b4][0], bb[b4][2]);
                MMA16816(acc[1][b4*2+1], ah1, bb[b4][1], bb[b4][3]);
                MMA16816(acc[0][b4*2],   al0, bb[b4][0], bb[b4][2]);
                MMA16816(acc[0][b4*2+1], al0, bb[b4][1], bb[b4][3]);
                MMA16816(acc[1][b4*2],   al1, bb[b4][0], bb[b4][2]);
                MMA16816(acc[1][b4*2+1], al1, bb[b4][1], bb[b4][3]);
            }
        }
    };

    // ---- pipeline ----
    LOADG(0);
    STORES(0);
    __syncthreads();
    int s = 0;
    for (int ch = 0; ch < NCH; ch++) {
        if (ch + 1 < NCH) LOADG(ch + 1);
        COMPUTE(s);
        if (ch + 1 < NCH) STORES(s ^ 1);
        __syncthreads();
        s ^= 1;
    }

    // ---- epilogue: write accum -> g_h ----
    const int gcol = g * CO + n_base + wn;
    const int r    = lane >> 2;
    const int c    = (lane & 3) * 2;
    #pragma unroll
    for (int mi = 0; mi < 2; mi++) {
        int m = m_base + wm + mi * 16 + r;
        #pragma unroll
        for (int nb = 0; nb < 8; nb++) {
            int n = gcol + nb * 8 + c;
            float2 v0 = make_float2(acc[mi][nb][0], acc[mi][nb][1]);
            float2 v1 = make_float2(acc[mi][nb][2], acc[mi][nb][3]);
            *(float2*)&g_h[(size_t)m * WW + n]       = v0;
            *(float2*)&g_h[(size_t)(m + 8) * WW + n] = v1;
        }
    }
}

// ============================================================
// Kernel 4: per-row LayerNorm + mask + projection dot
// ============================================================
__global__ void ln_proj_kernel(const float* __restrict__ conv_b,
                               const float* __restrict__ gamma,
                               const float* __restrict__ beta,
                               const float* __restrict__ proj_w,
                               const int* __restrict__ mask) {
    int row = blockIdx.x;
    int tid = threadIdx.x;   // 256
    const float* hr = &g_h[(size_t)row * WW];

    float v[4];
    float s = 0.f, ss = 0.f;
    #pragma unroll
    for (int i = 0; i < 4; i++) {
        int w = tid + i * 256;
        float hv = hr[w] + conv_b[w];
        v[i] = hv;
        s  += hv;
        ss += hv * hv;
    }
    __shared__ float shA[8], shB[8];
    __shared__ float mu_sh, rstd_sh;
    #pragma unroll
    for (int o = 16; o > 0; o >>= 1) {
        s  += __shfl_xor_sync(0xffffffff, s,  o);
        ss += __shfl_xor_sync(0xffffffff, ss, o);
    }
    int warp = tid >> 5, lane = tid & 31;
    if (lane == 0) { shA[warp] = s; shB[warp] = ss; }
    __syncthreads();
    if (tid == 0) {
        float S = 0.f, SS = 0.f;
        #pragma unroll
        for (int i = 0; i < 8; i++) { S += shA[i]; SS += shB[i]; }
        float mu = S / (float)WW;
        float var = SS / (float)WW - mu * mu;
        mu_sh = mu;
        rstd_sh = rsqrtf(var + 1e-5f);
    }
    __syncthreads();
    float mu = mu_sh, rstd = rstd_sh;

    float dot = 0.f;
    #pragma unroll
    for (int i = 0; i < 4; i++) {
        int w = tid + i * 256;
        dot += ((v[i] - mu) * rstd * gamma[w] + beta[w]) * proj_w[w];
    }
    #pragma unroll
    for (int o = 16; o > 0; o >>= 1)
        dot += __shfl_xor_sync(0xffffffff, dot, o);
    __syncthreads();
    if (lane == 0) shA[warp] = dot;
    __syncthreads();
    if (tid == 0) {
        float D = 0.f;
        #pragma unroll
        for (int i = 0; i < 8; i++) D += shA[i];
        g_s[row] = (mask[row] != 0) ? 0.f : D;
    }
}

// ============================================================
// Kernel 5: final masked mean over L + proj_b
// ============================================================
__global__ void final_kernel(const int* __restrict__ mask,
                             const float* __restrict__ proj_b,
                             float* __restrict__ out) {
    int b = blockIdx.x;
    int tid = threadIdx.x;  // 256
    float s = 0.f;
    int cnt = 0;
    for (int l = tid; l < LL; l += 256) {
        s += g_s[b * LL + l];
        cnt += (mask[b * LL + l] != 0) ? 0 : 1;
    }
    #pragma unroll
    for (int o = 16; o > 0; o >>= 1) {
        s   += __shfl_xor_sync(0xffffffff, s, o);
        cnt += __shfl_xor_sync(0xffffffff, cnt, o);
    }
    __shared__ float shS[8];
    __shared__ int   shC[8];
    int warp = tid >> 5, lane = tid & 31;
    if (lane == 0) { shS[warp] = s; shC[warp] = cnt; }
    __syncthreads();
    if (tid == 0) {
        float S = 0.f; int C = 0;
        #pragma unroll
        for (int i = 0; i < 8; i++) { S += shS[i]; C += shC[i]; }
        float len = fmaxf((float)C, 1.0f);
        out[b] = S / len + proj_b[0];
    }
}

// ============================================================
extern "C" void kernel_launch(void* const* d_in, const int* in_sizes, int n_in,
                              void* d_out, int out_size) {
    const float* x       = (const float*)d_in[0];
    const int*   mask    = (const int*)d_in[1];
    const float* w_off   = (const float*)d_in[2];
    const float* b_off   = (const float*)d_in[3];
    const float* conv_w  = (const float*)d_in[4];
    const float* conv_b  = (const float*)d_in[5];
    const float* gamma   = (const float*)d_in[6];
    const float* beta    = (const float*)d_in[7];
    const float* proj_w  = (const float*)d_in[8];
    const float* proj_b  = (const float*)d_in[9];
    float* out = (float*)d_out;

    cudaFuncSetAttribute(conv_mma_kernel,
                         cudaFuncAttributeMaxDynamicSharedMemorySize, SMEM_CONV);

    prep_b_kernel<<<(GG*CO*RDIM + 255) / 256, 256>>>(conv_w);
    offsets_kernel<<<BB * LL, 128>>>(x, w_off, b_off);
    dim3 cgrid(GG * 2, (BB * LL) / MT);   // (4, 128)
    conv_mma_kernel<<<cgrid, 512, SMEM_CONV>>>(x);
    ln_proj_kernel<<<BB * LL, 256>>>(conv_b, gamma, beta, proj_w, mask);
    final_kernel<<<BB, 256>>>(mask, proj_b, out);
}

// round 8
// speedup vs baseline: 2.6567x; 2.6567x over previous
#include <cuda_runtime.h>
#include <cuda_fp16.h>
#include <math.h>
#include <stdint.h>

#define BB 8
#define LL 2048
#define WW 1024
#define KK 5
#define GG 2
#define CI 512
#define CO 512
#define RDIM (KK*CI)        // 2560

// GEMM tiling
#define MT   128            // M per CTA
#define NTT  128            // N per CTA
#define KCB  32             // K-chunk (fp16 elems, 64B rows)
#define NCH  (RDIM/KCB)     // 80 chunks

// ---- static scratch ----
__device__ __half g_Bh[GG*CO*RDIM];           // [g][o][r] K-major fp16
__device__ int   g_p0[BB*LL*KK];
__device__ float g_frac[BB*LL*KK];
__device__ float g_h[(size_t)BB*LL*WW];       // conv output, 64 MB
__device__ float g_s[BB*LL];

// ============================================================
__device__ __forceinline__ uint32_t smem_u32(const void* p) {
    uint32_t a;
    asm("{ .reg .u64 t; cvta.to.shared.u64 t, %1; cvt.u32.u64 %0, t; }" : "=r"(a) : "l"(p));
    return a;
}
#define LDSM4(r, addr) \
    asm volatile("ldmatrix.sync.aligned.m8n8.x4.shared.b16 {%0,%1,%2,%3}, [%4];" \
        : "=r"((r)[0]), "=r"((r)[1]), "=r"((r)[2]), "=r"((r)[3]) : "r"(addr))
#define MMA16816(d, a, b0, b1) \
    asm volatile("mma.sync.aligned.m16n8k16.row.col.f32.f16.f16.f32 " \
        "{%0,%1,%2,%3}, {%4,%5,%6,%7}, {%8,%9}, {%0,%1,%2,%3};" \
        : "+f"((d)[0]), "+f"((d)[1]), "+f"((d)[2]), "+f"((d)[3]) \
        : "r"((a)[0]), "r"((a)[1]), "r"((a)[2]), "r"((a)[3]), "r"(b0), "r"(b1))

// ============================================================
// Kernel 1: B prep — conv_w [g][o][c][k] -> fp16 [g][o][r=k*CI+c]
// ============================================================
__global__ void prep_b_kernel(const float* __restrict__ conv_w) {
    int idx = blockIdx.x * 256 + threadIdx.x;
    if (idx >= GG*CO*RDIM) return;
    int r = idx % RDIM;
    int o = (idx / RDIM) % CO;
    int g = idx / (RDIM*CO);
    int k = r / CI, c = r % CI;
    float w = conv_w[(((g*CO + o)*CI + c)*KK) + k];
    g_Bh[idx] = __float2half_rn(w);
}

// ============================================================
// Kernel 2: offsets
// ============================================================
__global__ void offsets_kernel(const float* __restrict__ x,
                               const float* __restrict__ w_off,
                               const float* __restrict__ b_off) {
    int row = blockIdx.x;
    int tid = threadIdx.x;                // 128
    const float* xr = x + (size_t)row * WW;
    float acc[KK] = {0.f, 0.f, 0.f, 0.f, 0.f};
    for (int w = tid; w < WW; w += 128) {
        float xv = xr[w];
        #pragma unroll
        for (int k = 0; k < KK; k++) acc[k] += xv * w_off[w*KK + k];
    }
    __shared__ float sh[KK][128];
    #pragma unroll
    for (int k = 0; k < KK; k++) sh[k][tid] = acc[k];
    __syncthreads();
    for (int s = 64; s > 0; s >>= 1) {
        if (tid < s) {
            #pragma unroll
            for (int k = 0; k < KK; k++) sh[k][tid] += sh[k][tid + s];
        }
        __syncthreads();
    }
    if (tid < KK) {
        int k = tid;
        float off = tanhf(sh[k][0] + b_off[k]) * 2.0f;
        int l = row & (LL - 1);
        float pos = (float)l + ((float)k - 2.0f) + off;
        float p0 = floorf(pos);
        g_p0[row*KK + k]   = (int)p0;
        g_frac[row*KK + k] = pos - p0;
    }
}

// ============================================================
// Kernel 3: 2-term split-fp16 HMMA gathered GEMM
// grid (GG*4, 128); 512 threads = 16 warps (4m x 4n), warp tile 32x32
// SMEM stage (24KB): A_hi 8K | A_lo 8K | B 8K; 2 stages = 48KB
// rows are 64B (32 fp16); swizzle: grp16 ^= (row>>1)&3
// ============================================================
#define SA_HI(s) ((s)*24576 + 0)
#define SA_LO(s) ((s)*24576 + 8192)
#define SB(s)    ((s)*24576 + 16384)
#define SMEM_CONV (2*24576)

__global__ void __launch_bounds__(512) conv_mma_kernel(const float* __restrict__ x) {
    extern __shared__ __align__(128) char smem[];
    const uint32_t sb = smem_u32(smem);

    const int tid  = threadIdx.x;
    const int lane = tid & 31;
    const int wid  = tid >> 5;

    const int g      = blockIdx.x >> 2;
    const int n_base = (blockIdx.x & 3) * NTT;
    const int m_base = blockIdx.y * MT;

    // ---- loader mapping: thread t -> (row = t>>2, 8-col group = t&3) ----
    const int lrow = tid >> 2;
    const int lgrp = tid & 3;
    const int mg   = m_base + lrow;
    const float* xb = x + ((size_t)(mg >> 11)) * LL * WW + g * CI + lgrp * 8;
    const int*   p0p = &g_p0[mg * KK];
    const float* frp = &g_frac[mg * KK];
    const size_t gBrow = (size_t)(g * CO + n_base + lrow) * RDIM + lgrp * 8;
    const uint32_t offST = (uint32_t)(lrow * 64 + ((lgrp ^ ((lrow >> 1) & 3)) << 4));

    // ---- compute mapping ----
    const int wm = (wid & 3) * 32;       // warp m offset
    const int wn = (wid >> 2) * 32;      // warp n offset
    const int rA0 = wm + (lane & 15), rA1 = rA0 + 16;
    const int rB0 = wn + (lane & 15), rB1 = rB0 + 16;
    const int sA0 = (rA0 >> 1) & 3, sA1 = (rA1 >> 1) & 3;
    const int sB0 = (rB0 >> 1) & 3, sB1 = (rB1 >> 1) & 3;
    const int hi16 = lane >> 4;          // 0/1 -> +16B within k

    float acc[2][4][4];
    #pragma unroll
    for (int mi = 0; mi < 2; mi++)
        #pragma unroll
        for (int nt = 0; nt < 4; nt++)
            #pragma unroll
            for (int e = 0; e < 4; e++) acc[mi][nt][e] = 0.f;

    // staging registers
    float4 a00, a01, a10, a11;
    uint4 bhv;
    float lfrac;

    // ---- load chunk ch into staging regs ----
    auto LOADG = [&](int ch) {
        int ktap = ch >> 4;
        int c0   = (ch & 15) * KCB;
        int p0   = p0p[ktap];
        lfrac    = frp[ktap];
        int ok0 = (p0 >= 0) & (p0 < LL);
        int ok1 = (p0 >= -1) & (p0 < LL - 1);
        const float* pa = xb + c0 + (size_t)p0 * WW;
        float4 z = make_float4(0.f, 0.f, 0.f, 0.f);
        a00 = z; a01 = z; a10 = z; a11 = z;
        if (ok0) { a00 = *(const float4*)(pa);      a01 = *(const float4*)(pa + 4); }
        if (ok1) { a10 = *(const float4*)(pa + WW); a11 = *(const float4*)(pa + WW + 4); }
        bhv = *(const uint4*)(g_Bh + gBrow + ch * KCB);
    };

    // ---- convert staging regs and store to stage s ----
    auto STORES = [&](int s) {
        float w0 = 1.0f - lfrac, w1 = lfrac;
        float v[8];
        v[0] = a00.x*w0 + a10.x*w1; v[1] = a00.y*w0 + a10.y*w1;
        v[2] = a00.z*w0 + a10.z*w1; v[3] = a00.w*w0 + a10.w*w1;
        v[4] = a01.x*w0 + a11.x*w1; v[5] = a01.y*w0 + a11.y*w1;
        v[6] = a01.z*w0 + a11.z*w1; v[7] = a01.w*w0 + a11.w*w1;
        __half hv[8], lv[8];
        #pragma unroll
        for (int e = 0; e < 8; e++) {
            hv[e] = __float2half_rn(v[e]);
            lv[e] = __float2half_rn(v[e] - __half2float(hv[e]));
        }
        *(uint4*)(smem + SA_HI(s) + offST) = *(uint4*)hv;
        *(uint4*)(smem + SA_LO(s) + offST) = *(uint4*)lv;
        *(uint4*)(smem + SB(s) + offST) = bhv;
    };

    // ---- compute on stage s ----
    auto COMPUTE = [&](int s) {
        const uint32_t bAhi = sb + SA_HI(s), bAlo = sb + SA_LO(s), bBs = sb + SB(s);
        #pragma unroll
        for (int ks = 0; ks < 2; ks++) {
            const int grp = ks * 2 + hi16;
            const uint32_t oA0 = (uint32_t)(rA0 * 64 + ((grp ^ sA0) << 4));
            const uint32_t oA1 = (uint32_t)(rA1 * 64 + ((grp ^ sA1) << 4));
            const uint32_t oB0 = (uint32_t)(rB0 * 64 + ((grp ^ sB0) << 4));
            const uint32_t oB1 = (uint32_t)(rB1 * 64 + ((grp ^ sB1) << 4));
            uint32_t ah0[4], ah1[4], al0[4], al1[4];
            uint32_t bh0[4], bh1[4];
            LDSM4(ah0, bAhi + oA0);  LDSM4(ah1, bAhi + oA1);
            LDSM4(bh0, bBs + oB0);   LDSM4(bh1, bBs + oB1);
            LDSM4(al0, bAlo + oA0);  LDSM4(al1, bAlo + oA1);
            // hi * B
            MMA16816(acc[0][0], ah0, bh0[0], bh0[2]);
            MMA16816(acc[0][1], ah0, bh0[1], bh0[3]);
            MMA16816(acc[0][2], ah0, bh1[0], bh1[2]);
            MMA16816(acc[0][3], ah0, bh1[1], bh1[3]);
            MMA16816(acc[1][0], ah1, bh0[0], bh0[2]);
            MMA16816(acc[1][1], ah1, bh0[1], bh0[3]);
            MMA16816(acc[1][2], ah1, bh1[0], bh1[2]);
            MMA16816(acc[1][3], ah1, bh1[1], bh1[3]);
            // lo * B
            MMA16816(acc[0][0], al0, bh0[0], bh0[2]);
            MMA16816(acc[0][1], al0, bh0[1], bh0[3]);
            MMA16816(acc[0][2], al0, bh1[0], bh1[2]);
            MMA16816(acc[0][3], al0, bh1[1], bh1[3]);
            MMA16816(acc[1][0], al1, bh0[0], bh0[2]);
            MMA16816(acc[1][1], al1, bh0[1], bh0[3]);
            MMA16816(acc[1][2], al1, bh1[0], bh1[2]);
            MMA16816(acc[1][3], al1, bh1[1], bh1[3]);
        }
    };

    // ---- pipeline ----
    LOADG(0);
    STORES(0);
    __syncthreads();
    int s = 0;
    for (int ch = 0; ch < NCH; ch++) {
        if (ch + 1 < NCH) LOADG(ch + 1);
        COMPUTE(s);
        if (ch + 1 < NCH) STORES(s ^ 1);
        __syncthreads();
        s ^= 1;
    }

    // ---- epilogue: write accum -> g_h ----
    const int gcol = g * CO + n_base + wn;
    const int r    = lane >> 2;
    const int c    = (lane & 3) * 2;
    #pragma unroll
    for (int mi = 0; mi < 2; mi++) {
        int m = m_base + wm + mi * 16 + r;
        #pragma unroll
        for (int nt = 0; nt < 4; nt++) {
            int n = gcol + nt * 8 + c;
            float2 v0 = make_float2(acc[mi][nt][0], acc[mi][nt][1]);
            float2 v1 = make_float2(acc[mi][nt][2], acc[mi][nt][3]);
            *(float2*)&g_h[(size_t)m * WW + n]       = v0;
            *(float2*)&g_h[(size_t)(m + 8) * WW + n] = v1;
        }
    }
}

// ============================================================
// Kernel 4: per-row LayerNorm + mask + projection dot
// ============================================================
__global__ void ln_proj_kernel(const float* __restrict__ conv_b,
                               const float* __restrict__ gamma,
                               const float* __restrict__ beta,
                               const float* __restrict__ proj_w,
                               const int* __restrict__ mask) {
    int row = blockIdx.x;
    int tid = threadIdx.x;   // 256
    const float* hr = &g_h[(size_t)row * WW];

    float v[4];
    float s = 0.f, ss = 0.f;
    #pragma unroll
    for (int i = 0; i < 4; i++) {
        int w = tid + i * 256;
        float hv = hr[w] + conv_b[w];
        v[i] = hv;
        s  += hv;
        ss += hv * hv;
    }
    __shared__ float shA[8], shB[8];
    __shared__ float mu_sh, rstd_sh;
    #pragma unroll
    for (int o = 16; o > 0; o >>= 1) {
        s  += __shfl_xor_sync(0xffffffff, s,  o);
        ss += __shfl_xor_sync(0xffffffff, ss, o);
    }
    int warp = tid >> 5, lane = tid & 31;
    if (lane == 0) { shA[warp] = s; shB[warp] = ss; }
    __syncthreads();
    if (tid == 0) {
        float S = 0.f, SS = 0.f;
        #pragma unroll
        for (int i = 0; i < 8; i++) { S += shA[i]; SS += shB[i]; }
        float mu = S / (float)WW;
        float var = SS / (float)WW - mu * mu;
        mu_sh = mu;
        rstd_sh = rsqrtf(var + 1e-5f);
    }
    __syncthreads();
    float mu = mu_sh, rstd = rstd_sh;

    float dot = 0.f;
    #pragma unroll
    for (int i = 0; i < 4; i++) {
        int w = tid + i * 256;
        dot += ((v[i] - mu) * rstd * gamma[w] + beta[w]) * proj_w[w];
    }
    #pragma unroll
    for (int o = 16; o > 0; o >>= 1)
        dot += __shfl_xor_sync(0xffffffff, dot, o);
    __syncthreads();
    if (lane == 0) shA[warp] = dot;
    __syncthreads();
    if (tid == 0) {
        float D = 0.f;
        #pragma unroll
        for (int i = 0; i < 8; i++) D += shA[i];
        g_s[row] = (mask[row] != 0) ? 0.f : D;
    }
}

// ============================================================
// Kernel 5: final masked mean over L + proj_b
// ============================================================
__global__ void final_kernel(const int* __restrict__ mask,
                             const float* __restrict__ proj_b,
                             float* __restrict__ out) {
    int b = blockIdx.x;
    int tid = threadIdx.x;  // 256
    float s = 0.f;
    int cnt = 0;
    for (int l = tid; l < LL; l += 256) {
        s += g_s[b * LL + l];
        cnt += (mask[b * LL + l] != 0) ? 0 : 1;
    }
    #pragma unroll
    for (int o = 16; o > 0; o >>= 1) {
        s   += __shfl_xor_sync(0xffffffff, s, o);
        cnt += __shfl_xor_sync(0xffffffff, cnt, o);
    }
    __shared__ float shS[8];
    __shared__ int   shC[8];
    int warp = tid >> 5, lane = tid & 31;
    if (lane == 0) { shS[warp] = s; shC[warp] = cnt; }
    __syncthreads();
    if (tid == 0) {
        float S = 0.f; int C = 0;
        #pragma unroll
        for (int i = 0; i < 8; i++) { S += shS[i]; C += shC[i]; }
        float len = fmaxf((float)C, 1.0f);
        out[b] = S / len + proj_b[0];
    }
}

// ============================================================
extern "C" void kernel_launch(void* const* d_in, const int* in_sizes, int n_in,
                              void* d_out, int out_size) {
    const float* x       = (const float*)d_in[0];
    const int*   mask    = (const int*)d_in[1];
    const float* w_off   = (const float*)d_in[2];
    const float* b_off   = (const float*)d_in[3];
    const float* conv_w  = (const float*)d_in[4];
    const float* conv_b  = (const float*)d_in[5];
    const float* gamma   = (const float*)d_in[6];
    const float* beta    = (const float*)d_in[7];
    const float* proj_w  = (const float*)d_in[8];
    const float* proj_b  = (const float*)d_in[9];
    float* out = (float*)d_out;

    cudaFuncSetAttribute(conv_mma_kernel,
                         cudaFuncAttributeMaxDynamicSharedMemorySize, SMEM_CONV);

    prep_b_kernel<<<(GG*CO*RDIM + 255) / 256, 256>>>(conv_w);
    offsets_kernel<<<BB * LL, 128>>>(x, w_off, b_off);
    dim3 cgrid(GG * 4, (BB * LL) / MT);   // (8, 128)
    conv_mma_kernel<<<cgrid, 512, SMEM_CONV>>>(x);
    ln_proj_kernel<<<BB * LL, 256>>>(conv_b, gamma, beta, proj_w, mask);
    final_kernel<<<BB, 256>>>(mask, proj_b, out);
}

// round 10
// speedup vs baseline: 3.2337x; 1.2172x over previous
#include <cuda_runtime.h>
#include <cuda_fp16.h>
#include <math.h>
#include <stdint.h>

#define BB 8
#define LL 2048
#define WW 1024
#define KK 5
#define GG 2
#define CI 512
#define CO 512
#define RDIM (KK*CI)        // 2560

// GEMM tiling
#define MT   128            // M per CTA
#define NTT  128            // N per CTA
#define KCB  32             // K-chunk (fp16 elems, 64B rows)
#define NCH  (RDIM/KCB)     // 80 chunks

// ---- static scratch ----
__device__ __half g_Bh[GG*CO*RDIM];           // [g][o][r] K-major fp16
__device__ int   g_p0[BB*LL*KK];
__device__ float g_frac[BB*LL*KK];
__device__ float g_h[(size_t)BB*LL*WW];       // conv output, 64 MB
__device__ float g_s[BB*LL];

// ============================================================
__device__ __forceinline__ uint32_t smem_u32(const void* p) {
    uint32_t a;
    asm("{ .reg .u64 t; cvta.to.shared.u64 t, %1; cvt.u32.u64 %0, t; }" : "=r"(a) : "l"(p));
    return a;
}
#define LDSM4(r, addr) \
    asm volatile("ldmatrix.sync.aligned.m8n8.x4.shared.b16 {%0,%1,%2,%3}, [%4];" \
        : "=r"((r)[0]), "=r"((r)[1]), "=r"((r)[2]), "=r"((r)[3]) : "r"(addr))
#define MMA16816(d, a, b0, b1) \
    asm volatile("mma.sync.aligned.m16n8k16.row.col.f32.f16.f16.f32 " \
        "{%0,%1,%2,%3}, {%4,%5,%6,%7}, {%8,%9}, {%0,%1,%2,%3};" \
        : "+f"((d)[0]), "+f"((d)[1]), "+f"((d)[2]), "+f"((d)[3]) \
        : "r"((a)[0]), "r"((a)[1]), "r"((a)[2]), "r"((a)[3]), "r"(b0), "r"(b1))

// ============================================================
// Kernel 1: B prep — conv_w [g][o][c][k] -> fp16 [g][o][r=k*CI+c]
// ============================================================
__global__ void prep_b_kernel(const float* __restrict__ conv_w) {
    int idx = blockIdx.x * 256 + threadIdx.x;
    if (idx >= GG*CO*RDIM) return;
    int r = idx % RDIM;
    int o = (idx / RDIM) % CO;
    int g = idx / (RDIM*CO);
    int k = r / CI, c = r % CI;
    float w = conv_w[(((g*CO + o)*CI + c)*KK) + k];
    g_Bh[idx] = __float2half_rn(w);
}

// ============================================================
// Kernel 2: offsets
// ============================================================
__global__ void offsets_kernel(const float* __restrict__ x,
                               const float* __restrict__ w_off,
                               const float* __restrict__ b_off) {
    int row = blockIdx.x;
    int tid = threadIdx.x;                // 128
    const float* xr = x + (size_t)row * WW;
    float acc[KK] = {0.f, 0.f, 0.f, 0.f, 0.f};
    for (int w = tid; w < WW; w += 128) {
        float xv = xr[w];
        #pragma unroll
        for (int k = 0; k < KK; k++) acc[k] += xv * w_off[w*KK + k];
    }
    __shared__ float sh[KK][128];
    #pragma unroll
    for (int k = 0; k < KK; k++) sh[k][tid] = acc[k];
    __syncthreads();
    for (int s = 64; s > 0; s >>= 1) {
        if (tid < s) {
            #pragma unroll
            for (int k = 0; k < KK; k++) sh[k][tid] += sh[k][tid + s];
        }
        __syncthreads();
    }
    if (tid < KK) {
        int k = tid;
        float off = tanhf(sh[k][0] + b_off[k]) * 2.0f;
        int l = row & (LL - 1);
        float pos = (float)l + ((float)k - 2.0f) + off;
        float p0 = floorf(pos);
        g_p0[row*KK + k]   = (int)p0;
        g_frac[row*KK + k] = pos - p0;
    }
}

// ============================================================
// Kernel 3: single-fp16 HMMA gathered GEMM
// grid (GG*4, 128); 512 threads = 16 warps (4m x 4n), warp tile 32x32
// SMEM stage (16KB): A 8K | B 8K; 2 stages = 32KB
// rows are 64B (32 fp16); swizzle: grp16 ^= (row>>1)&3
// ============================================================
#define SA(s)   ((s)*16384 + 0)
#define SB(s)   ((s)*16384 + 8192)
#define SMEM_CONV (2*16384)

__global__ void __launch_bounds__(512) conv_mma_kernel(const float* __restrict__ x) {
    extern __shared__ __align__(128) char smem[];
    const uint32_t sb = smem_u32(smem);

    const int tid  = threadIdx.x;
    const int lane = tid & 31;
    const int wid  = tid >> 5;

    const int g      = blockIdx.x >> 2;
    const int n_base = (blockIdx.x & 3) * NTT;
    const int m_base = blockIdx.y * MT;

    // ---- loader mapping: thread t -> (row = t>>2, 8-col group = t&3) ----
    const int lrow = tid >> 2;
    const int lgrp = tid & 3;
    const int mg   = m_base + lrow;
    const float* xb = x + ((size_t)(mg >> 11)) * LL * WW + g * CI + lgrp * 8;
    const int*   p0p = &g_p0[mg * KK];
    const float* frp = &g_frac[mg * KK];
    const size_t gBrow = (size_t)(g * CO + n_base + lrow) * RDIM + lgrp * 8;
    const uint32_t offST = (uint32_t)(lrow * 64 + ((lgrp ^ ((lrow >> 1) & 3)) << 4));

    // ---- compute mapping ----
    const int wm = (wid & 3) * 32;       // warp m offset
    const int wn = (wid >> 2) * 32;      // warp n offset
    const int rA0 = wm + (lane & 15), rA1 = rA0 + 16;
    const int rB0 = wn + (lane & 15), rB1 = rB0 + 16;
    const int sA0 = (rA0 >> 1) & 3, sA1 = (rA1 >> 1) & 3;
    const int sB0 = (rB0 >> 1) & 3, sB1 = (rB1 >> 1) & 3;
    const int hi16 = lane >> 4;          // 0/1 -> +16B within k

    float acc[2][4][4];
    #pragma unroll
    for (int mi = 0; mi < 2; mi++)
        #pragma unroll
        for (int nt = 0; nt < 4; nt++)
            #pragma unroll
            for (int e = 0; e < 4; e++) acc[mi][nt][e] = 0.f;

    // staging registers
    float4 a00, a01, a10, a11;
    uint4 bhv;
    float lfrac;

    // ---- load chunk ch into staging regs ----
    auto LOADG = [&](int ch) {
        int ktap = ch >> 4;
        int c0   = (ch & 15) * KCB;
        int p0   = p0p[ktap];
        lfrac    = frp[ktap];
        int ok0 = (p0 >= 0) & (p0 < LL);
        int ok1 = (p0 >= -1) & (p0 < LL - 1);
        const float* pa = xb + c0 + (size_t)p0 * WW;
        float4 z = make_float4(0.f, 0.f, 0.f, 0.f);
        a00 = z; a01 = z; a10 = z; a11 = z;
        if (ok0) { a00 = *(const float4*)(pa);      a01 = *(const float4*)(pa + 4); }
        if (ok1) { a10 = *(const float4*)(pa + WW); a11 = *(const float4*)(pa + WW + 4); }
        bhv = *(const uint4*)(g_Bh + gBrow + ch * KCB);
    };

    // ---- convert staging regs and store to stage s ----
    auto STORES = [&](int s) {
        float w0 = 1.0f - lfrac, w1 = lfrac;
        float v[8];
        v[0] = a00.x*w0 + a10.x*w1; v[1] = a00.y*w0 + a10.y*w1;
        v[2] = a00.z*w0 + a10.z*w1; v[3] = a00.w*w0 + a10.w*w1;
        v[4] = a01.x*w0 + a11.x*w1; v[5] = a01.y*w0 + a11.y*w1;
        v[6] = a01.z*w0 + a11.z*w1; v[7] = a01.w*w0 + a11.w*w1;
        __half hv[8];
        #pragma unroll
        for (int e = 0; e < 8; e++) hv[e] = __float2half_rn(v[e]);
        *(uint4*)(smem + SA(s) + offST) = *(uint4*)hv;
        *(uint4*)(smem + SB(s) + offST) = bhv;
    };

    // ---- compute on stage s ----
    auto COMPUTE = [&](int s) {
        const uint32_t bAs = sb + SA(s), bBs = sb + SB(s);
        #pragma unroll
        for (int ks = 0; ks < 2; ks++) {
            const int grp = ks * 2 + hi16;
            const uint32_t oA0 = (uint32_t)(rA0 * 64 + ((grp ^ sA0) << 4));
            const uint32_t oA1 = (uint32_t)(rA1 * 64 + ((grp ^ sA1) << 4));
            const uint32_t oB0 = (uint32_t)(rB0 * 64 + ((grp ^ sB0) << 4));
            const uint32_t oB1 = (uint32_t)(rB1 * 64 + ((grp ^ sB1) << 4));
            uint32_t ah0[4], ah1[4], bh0[4], bh1[4];
            LDSM4(ah0, bAs + oA0);  LDSM4(ah1, bAs + oA1);
            LDSM4(bh0, bBs + oB0);  LDSM4(bh1, bBs + oB1);
            MMA16816(acc[0][0], ah0, bh0[0], bh0[2]);
            MMA16816(acc[0][1], ah0, bh0[1], bh0[3]);
            MMA16816(acc[0][2], ah0, bh1[0], bh1[2]);
            MMA16816(acc[0][3], ah0, bh1[1], bh1[3]);
            MMA16816(acc[1][0], ah1, bh0[0], bh0[2]);
            MMA16816(acc[1][1], ah1, bh0[1], bh0[3]);
            MMA16816(acc[1][2], ah1, bh1[0], bh1[2]);
            MMA16816(acc[1][3], ah1, bh1[1], bh1[3]);
        }
    };

    // ---- pipeline ----
    LOADG(0);
    STORES(0);
    __syncthreads();
    int s = 0;
    for (int ch = 0; ch < NCH; ch++) {
        if (ch + 1 < NCH) LOADG(ch + 1);
        COMPUTE(s);
        if (ch + 1 < NCH) STORES(s ^ 1);
        __syncthreads();
        s ^= 1;
    }

    // ---- epilogue: write accum -> g_h ----
    const int gcol = g * CO + n_base + wn;
    const int r    = lane >> 2;
    const int c    = (lane & 3) * 2;
    #pragma unroll
    for (int mi = 0; mi < 2; mi++) {
        int m = m_base + wm + mi * 16 + r;
        #pragma unroll
        for (int nt = 0; nt < 4; nt++) {
            int n = gcol + nt * 8 + c;
            float2 v0 = make_float2(acc[mi][nt][0], acc[mi][nt][1]);
            float2 v1 = make_float2(acc[mi][nt][2], acc[mi][nt][3]);
            *(float2*)&g_h[(size_t)m * WW + n]       = v0;
            *(float2*)&g_h[(size_t)(m + 8) * WW + n] = v1;
        }
    }
}

// ============================================================
// Kernel 4: per-row LayerNorm + mask + projection dot
// ============================================================
__global__ void ln_proj_kernel(const float* __restrict__ conv_b,
                               const float* __restrict__ gamma,
                               const float* __restrict__ beta,
                               const float* __restrict__ proj_w,
                               const int* __restrict__ mask) {
    int row = blockIdx.x;
    int tid = threadIdx.x;   // 256
    const float* hr = &g_h[(size_t)row * WW];

    float v[4];
    float s = 0.f, ss = 0.f;
    #pragma unroll
    for (int i = 0; i < 4; i++) {
        int w = tid + i * 256;
        float hv = hr[w] + conv_b[w];
        v[i] = hv;
        s  += hv;
        ss += hv * hv;
    }
    __shared__ float shA[8], shB[8];
    __shared__ float mu_sh, rstd_sh;
    #pragma unroll
    for (int o = 16; o > 0; o >>= 1) {
        s  += __shfl_xor_sync(0xffffffff, s,  o);
        ss += __shfl_xor_sync(0xffffffff, ss, o);
    }
    int warp = tid >> 5, lane = tid & 31;
    if (lane == 0) { shA[warp] = s; shB[warp] = ss; }
    __syncthreads();
    if (tid == 0) {
        float S = 0.f, SS = 0.f;
        #pragma unroll
        for (int i = 0; i < 8; i++) { S += shA[i]; SS += shB[i]; }
        float mu = S / (float)WW;
        float var = SS / (float)WW - mu * mu;
        mu_sh = mu;
        rstd_sh = rsqrtf(var + 1e-5f);
    }
    __syncthreads();
    float mu = mu_sh, rstd = rstd_sh;

    float dot = 0.f;
    #pragma unroll
    for (int i = 0; i < 4; i++) {
        int w = tid + i * 256;
        dot += ((v[i] - mu) * rstd * gamma[w] + beta[w]) * proj_w[w];
    }
    #pragma unroll
    for (int o = 16; o > 0; o >>= 1)
        dot += __shfl_xor_sync(0xffffffff, dot, o);
    __syncthreads();
    if (lane == 0) shA[warp] = dot;
    __syncthreads();
    if (tid == 0) {
        float D = 0.f;
        #pragma unroll
        for (int i = 0; i < 8; i++) D += shA[i];
        g_s[row] = (mask[row] != 0) ? 0.f : D;
    }
}

// ============================================================
// Kernel 5: final masked mean over L + proj_b
// ============================================================
__global__ void final_kernel(const int* __restrict__ mask,
                             const float* __restrict__ proj_b,
                             float* __restrict__ out) {
    int b = blockIdx.x;
    int tid = threadIdx.x;  // 256
    float s = 0.f;
    int cnt = 0;
    for (int l = tid; l < LL; l += 256) {
        s += g_s[b * LL + l];
        cnt += (mask[b * LL + l] != 0) ? 0 : 1;
    }
    #pragma unroll
    for (int o = 16; o > 0; o >>= 1) {
        s   += __shfl_xor_sync(0xffffffff, s, o);
        cnt += __shfl_xor_sync(0xffffffff, cnt, o);
    }
    __shared__ float shS[8];
    __shared__ int   shC[8];
    int warp = tid >> 5, lane = tid & 31;
    if (lane == 0) { shS[warp] = s; shC[warp] = cnt; }
    __syncthreads();
    if (tid == 0) {
        float S = 0.f; int C = 0;
        #pragma unroll
        for (int i = 0; i < 8; i++) { S += shS[i]; C += shC[i]; }
        float len = fmaxf((float)C, 1.0f);
        out[b] = S / len + proj_b[0];
    }
}

// ============================================================
extern "C" void kernel_launch(void* const* d_in, const int* in_sizes, int n_in,
                              void* d_out, int out_size) {
    const float* x       = (const float*)d_in[0];
    const int*   mask    = (const int*)d_in[1];
    const float* w_off   = (const float*)d_in[2];
    const float* b_off   = (const float*)d_in[3];
    const float* conv_w  = (const float*)d_in[4];
    const float* conv_b  = (const float*)d_in[5];
    const float* gamma   = (const float*)d_in[6];
    const float* beta    = (const float*)d_in[7];
    const float* proj_w  = (const float*)d_in[8];
    const float* proj_b  = (const float*)d_in[9];
    float* out = (float*)d_out;

    cudaFuncSetAttribute(conv_mma_kernel,
                         cudaFuncAttributeMaxDynamicSharedMemorySize, SMEM_CONV);

    prep_b_kernel<<<(GG*CO*RDIM + 255) / 256, 256>>>(conv_w);
    offsets_kernel<<<BB * LL, 128>>>(x, w_off, b_off);
    dim3 cgrid(GG * 4, (BB * LL) / MT);   // (8, 128)
    conv_mma_kernel<<<cgrid, 512, SMEM_CONV>>>(x);
    ln_proj_kernel<<<BB * LL, 256>>>(conv_b, gamma, beta, proj_w, mask);
    final_kernel<<<BB, 256>>>(mask, proj_b, out);
}

// round 11
// speedup vs baseline: 3.4574x; 1.0692x over previous
#include <cuda_runtime.h>
#include <cuda_fp16.h>
#include <math.h>
#include <stdint.h>

#define BB 8
#define LL 2048
#define WW 1024
#define KK 5
#define GG 2
#define CI 512
#define CO 512
#define RDIM (KK*CI)        // 2560

// GEMM tiling
#define MT   128            // M per CTA
#define NTT  128            // N per CTA
#define KCB  32             // K-chunk (fp16 elems, 64B rows)
#define NCH  (RDIM/KCB)     // 80 chunks

// ---- static scratch ----
__device__ __half g_Bh[GG*CO*RDIM];           // [g][o][r] K-major fp16
__device__ __half g_xh[(size_t)BB*LL*WW];     // fp16 copy of x, 32 MB
__device__ int   g_p0[BB*LL*KK];
__device__ float g_frac[BB*LL*KK];
__device__ float g_h[(size_t)BB*LL*WW];       // conv output, 64 MB
__device__ float g_s[BB*LL];

// ============================================================
__device__ __forceinline__ uint32_t smem_u32(const void* p) {
    uint32_t a;
    asm("{ .reg .u64 t; cvta.to.shared.u64 t, %1; cvt.u32.u64 %0, t; }" : "=r"(a) : "l"(p));
    return a;
}
#define LDSM4(r, addr) \
    asm volatile("ldmatrix.sync.aligned.m8n8.x4.shared.b16 {%0,%1,%2,%3}, [%4];" \
        : "=r"((r)[0]), "=r"((r)[1]), "=r"((r)[2]), "=r"((r)[3]) : "r"(addr))
#define MMA16816(d, a, b0, b1) \
    asm volatile("mma.sync.aligned.m16n8k16.row.col.f32.f16.f16.f32 " \
        "{%0,%1,%2,%3}, {%4,%5,%6,%7}, {%8,%9}, {%0,%1,%2,%3};" \
        : "+f"((d)[0]), "+f"((d)[1]), "+f"((d)[2]), "+f"((d)[3]) \
        : "r"((a)[0]), "r"((a)[1]), "r"((a)[2]), "r"((a)[3]), "r"(b0), "r"(b1))

// ============================================================
// Kernel 0: x -> fp16 copy
// ============================================================
__global__ void xconv_kernel(const float* __restrict__ x) {
    size_t i = ((size_t)blockIdx.x * 256 + threadIdx.x) * 4;
    float4 v = *(const float4*)(x + i);
    __half2 h0 = __floats2half2_rn(v.x, v.y);
    __half2 h1 = __floats2half2_rn(v.z, v.w);
    *(uint2*)(g_xh + i) = make_uint2(*(uint32_t*)&h0, *(uint32_t*)&h1);
}

// ============================================================
// Kernel 1: B prep — conv_w [g][o][c][k] -> fp16 [g][o][r=k*CI+c]
// ============================================================
__global__ void prep_b_kernel(const float* __restrict__ conv_w) {
    int idx = blockIdx.x * 256 + threadIdx.x;
    if (idx >= GG*CO*RDIM) return;
    int r = idx % RDIM;
    int o = (idx / RDIM) % CO;
    int g = idx / (RDIM*CO);
    int k = r / CI, c = r % CI;
    float w = conv_w[(((g*CO + o)*CI + c)*KK) + k];
    g_Bh[idx] = __float2half_rn(w);
}

// ============================================================
// Kernel 2: offsets
// ============================================================
__global__ void offsets_kernel(const float* __restrict__ x,
                               const float* __restrict__ w_off,
                               const float* __restrict__ b_off) {
    int row = blockIdx.x;
    int tid = threadIdx.x;                // 128
    const float* xr = x + (size_t)row * WW;
    float acc[KK] = {0.f, 0.f, 0.f, 0.f, 0.f};
    for (int w = tid; w < WW; w += 128) {
        float xv = xr[w];
        #pragma unroll
        for (int k = 0; k < KK; k++) acc[k] += xv * w_off[w*KK + k];
    }
    __shared__ float sh[KK][128];
    #pragma unroll
    for (int k = 0; k < KK; k++) sh[k][tid] = acc[k];
    __syncthreads();
    for (int s = 64; s > 0; s >>= 1) {
        if (tid < s) {
            #pragma unroll
            for (int k = 0; k < KK; k++) sh[k][tid] += sh[k][tid + s];
        }
        __syncthreads();
    }
    if (tid < KK) {
        int k = tid;
        float off = tanhf(sh[k][0] + b_off[k]) * 2.0f;
        int l = row & (LL - 1);
        float pos = (float)l + ((float)k - 2.0f) + off;
        float p0 = floorf(pos);
        g_p0[row*KK + k]   = (int)p0;
        g_frac[row*KK + k] = pos - p0;
    }
}

// ============================================================
// Kernel 3: single-fp16 HMMA gathered GEMM (gathers from fp16 x)
// grid (GG*4, 128); 512 threads = 16 warps (4m x 4n), warp tile 32x32
// SMEM stage (16KB): A 8K | B 8K; 2 stages = 32KB
// rows are 64B (32 fp16); swizzle: grp16 ^= (row>>1)&3
// ============================================================
#define SA(s)   ((s)*16384 + 0)
#define SB(s)   ((s)*16384 + 8192)
#define SMEM_CONV (2*16384)

__global__ void __launch_bounds__(512) conv_mma_kernel() {
    extern __shared__ __align__(128) char smem[];
    const uint32_t sb = smem_u32(smem);

    const int tid  = threadIdx.x;
    const int lane = tid & 31;
    const int wid  = tid >> 5;

    const int g      = blockIdx.x >> 2;
    const int n_base = (blockIdx.x & 3) * NTT;
    const int m_base = blockIdx.y * MT;

    // ---- loader mapping: thread t -> (row = t>>2, 8-col group = t&3) ----
    const int lrow = tid >> 2;
    const int lgrp = tid & 3;
    const int mg   = m_base + lrow;
    const __half* xb = g_xh + ((size_t)(mg >> 11)) * LL * WW + g * CI + lgrp * 8;
    const int*   p0p = &g_p0[mg * KK];
    const float* frp = &g_frac[mg * KK];
    const size_t gBrow = (size_t)(g * CO + n_base + lrow) * RDIM + lgrp * 8;
    const uint32_t offST = (uint32_t)(lrow * 64 + ((lgrp ^ ((lrow >> 1) & 3)) << 4));

    // ---- compute mapping ----
    const int wm = (wid & 3) * 32;       // warp m offset
    const int wn = (wid >> 2) * 32;      // warp n offset
    const int rA0 = wm + (lane & 15), rA1 = rA0 + 16;
    const int rB0 = wn + (lane & 15), rB1 = rB0 + 16;
    const int sA0 = (rA0 >> 1) & 3, sA1 = (rA1 >> 1) & 3;
    const int sB0 = (rB0 >> 1) & 3, sB1 = (rB1 >> 1) & 3;
    const int hi16 = lane >> 4;          // 0/1 -> +16B within k

    float acc[2][4][4];
    #pragma unroll
    for (int mi = 0; mi < 2; mi++)
        #pragma unroll
        for (int nt = 0; nt < 4; nt++)
            #pragma unroll
            for (int e = 0; e < 4; e++) acc[mi][nt][e] = 0.f;

    // staging registers
    uint4 xv0, xv1, bhv;
    float lfrac;

    // ---- load chunk ch into staging regs ----
    auto LOADG = [&](int ch) {
        int ktap = ch >> 4;
        int c0   = (ch & 15) * KCB;
        int p0   = p0p[ktap];
        lfrac    = frp[ktap];
        int ok0 = (p0 >= 0) & (p0 < LL);
        int ok1 = (p0 >= -1) & (p0 < LL - 1);
        const __half* pa = xb + c0 + (size_t)p0 * WW;
        uint4 z = make_uint4(0u, 0u, 0u, 0u);
        xv0 = z; xv1 = z;
        if (ok0) xv0 = *(const uint4*)(pa);
        if (ok1) xv1 = *(const uint4*)(pa + WW);
        bhv = *(const uint4*)(g_Bh + gBrow + ch * KCB);
    };

    // ---- convert staging regs and store to stage s ----
    auto STORES = [&](int s) {
        float w0 = 1.0f - lfrac, w1 = lfrac;
        const __half2* h0 = (const __half2*)&xv0;
        const __half2* h1 = (const __half2*)&xv1;
        __half2 hv[4];
        #pragma unroll
        for (int e = 0; e < 4; e++) {
            float2 f0 = __half22float2(h0[e]);
            float2 f1 = __half22float2(h1[e]);
            hv[e] = __floats2half2_rn(f0.x * w0 + f1.x * w1,
                                      f0.y * w0 + f1.y * w1);
        }
        *(uint4*)(smem + SA(s) + offST) = *(uint4*)hv;
        *(uint4*)(smem + SB(s) + offST) = bhv;
    };

    // ---- compute on stage s ----
    auto COMPUTE = [&](int s) {
        const uint32_t bAs = sb + SA(s), bBs = sb + SB(s);
        #pragma unroll
        for (int ks = 0; ks < 2; ks++) {
            const int grp = ks * 2 + hi16;
            const uint32_t oA0 = (uint32_t)(rA0 * 64 + ((grp ^ sA0) << 4));
            const uint32_t oA1 = (uint32_t)(rA1 * 64 + ((grp ^ sA1) << 4));
            const uint32_t oB0 = (uint32_t)(rB0 * 64 + ((grp ^ sB0) << 4));
            const uint32_t oB1 = (uint32_t)(rB1 * 64 + ((grp ^ sB1) << 4));
            uint32_t ah0[4], ah1[4], bh0[4], bh1[4];
            LDSM4(ah0, bAs + oA0);  LDSM4(ah1, bAs + oA1);
            LDSM4(bh0, bBs + oB0);  LDSM4(bh1, bBs + oB1);
            MMA16816(acc[0][0], ah0, bh0[0], bh0[2]);
            MMA16816(acc[0][1], ah0, bh0[1], bh0[3]);
            MMA16816(acc[0][2], ah0, bh1[0], bh1[2]);
            MMA16816(acc[0][3], ah0, bh1[1], bh1[3]);
            MMA16816(acc[1][0], ah1, bh0[0], bh0[2]);
            MMA16816(acc[1][1], ah1, bh0[1], bh0[3]);
            MMA16816(acc[1][2], ah1, bh1[0], bh1[2]);
            MMA16816(acc[1][3], ah1, bh1[1], bh1[3]);
        }
    };

    // ---- pipeline ----
    LOADG(0);
    STORES(0);
    __syncthreads();
    int s = 0;
    for (int ch = 0; ch < NCH; ch++) {
        if (ch + 1 < NCH) LOADG(ch + 1);
        COMPUTE(s);
        if (ch + 1 < NCH) STORES(s ^ 1);
        __syncthreads();
        s ^= 1;
    }

    // ---- epilogue: write accum -> g_h ----
    const int gcol = g * CO + n_base + wn;
    const int r    = lane >> 2;
    const int c    = (lane & 3) * 2;
    #pragma unroll
    for (int mi = 0; mi < 2; mi++) {
        int m = m_base + wm + mi * 16 + r;
        #pragma unroll
        for (int nt = 0; nt < 4; nt++) {
            int n = gcol + nt * 8 + c;
            float2 v0 = make_float2(acc[mi][nt][0], acc[mi][nt][1]);
            float2 v1 = make_float2(acc[mi][nt][2], acc[mi][nt][3]);
            *(float2*)&g_h[(size_t)m * WW + n]       = v0;
            *(float2*)&g_h[(size_t)(m + 8) * WW + n] = v1;
        }
    }
}

// ============================================================
// Kernel 4: per-row LayerNorm + mask + projection dot
// ============================================================
__global__ void ln_proj_kernel(const float* __restrict__ conv_b,
                               const float* __restrict__ gamma,
                               const float* __restrict__ beta,
                               const float* __restrict__ proj_w,
                               const int* __restrict__ mask) {
    int row = blockIdx.x;
    int tid = threadIdx.x;   // 256
    const float* hr = &g_h[(size_t)row * WW];

    float v[4];
    float s = 0.f, ss = 0.f;
    #pragma unroll
    for (int i = 0; i < 4; i++) {
        int w = tid + i * 256;
        float hv = hr[w] + conv_b[w];
        v[i] = hv;
        s  += hv;
        ss += hv * hv;
    }
    __shared__ float shA[8], shB[8];
    __shared__ float mu_sh, rstd_sh;
    #pragma unroll
    for (int o = 16; o > 0; o >>= 1) {
        s  += __shfl_xor_sync(0xffffffff, s,  o);
        ss += __shfl_xor_sync(0xffffffff, ss, o);
    }
    int warp = tid >> 5, lane = tid & 31;
    if (lane == 0) { shA[warp] = s; shB[warp] = ss; }
    __syncthreads();
    if (tid == 0) {
        float S = 0.f, SS = 0.f;
        #pragma unroll
        for (int i = 0; i < 8; i++) { S += shA[i]; SS += shB[i]; }
        float mu = S / (float)WW;
        float var = SS / (float)WW - mu * mu;
        mu_sh = mu;
        rstd_sh = rsqrtf(var + 1e-5f);
    }
    __syncthreads();
    float mu = mu_sh, rstd = rstd_sh;

    float dot = 0.f;
    #pragma unroll
    for (int i = 0; i < 4; i++) {
        int w = tid + i * 256;
        dot += ((v[i] - mu) * rstd * gamma[w] + beta[w]) * proj_w[w];
    }
    #pragma unroll
    for (int o = 16; o > 0; o >>= 1)
        dot += __shfl_xor_sync(0xffffffff, dot, o);
    __syncthreads();
    if (lane == 0) shA[warp] = dot;
    __syncthreads();
    if (tid == 0) {
        float D = 0.f;
        #pragma unroll
        for (int i = 0; i < 8; i++) D += shA[i];
        g_s[row] = (mask[row] != 0) ? 0.f : D;
    }
}

// ============================================================
// Kernel 5: final masked mean over L + proj_b
// ============================================================
__global__ void final_kernel(const int* __restrict__ mask,
                             const float* __restrict__ proj_b,
                             float* __restrict__ out) {
    int b = blockIdx.x;
    int tid = threadIdx.x;  // 256
    float s = 0.f;
    int cnt = 0;
    for (int l = tid; l < LL; l += 256) {
        s += g_s[b * LL + l];
        cnt += (mask[b * LL + l] != 0) ? 0 : 1;
    }
    #pragma unroll
    for (int o = 16; o > 0; o >>= 1) {
        s   += __shfl_xor_sync(0xffffffff, s, o);
        cnt += __shfl_xor_sync(0xffffffff, cnt, o);
    }
    __shared__ float shS[8];
    __shared__ int   shC[8];
    int warp = tid >> 5, lane = tid & 31;
    if (lane == 0) { shS[warp] = s; shC[warp] = cnt; }
    __syncthreads();
    if (tid == 0) {
        float S = 0.f; int C = 0;
        #pragma unroll
        for (int i = 0; i < 8; i++) { S += shS[i]; C += shC[i]; }
        float len = fmaxf((float)C, 1.0f);
        out[b] = S / len + proj_b[0];
    }
}

// ============================================================
extern "C" void kernel_launch(void* const* d_in, const int* in_sizes, int n_in,
                              void* d_out, int out_size) {
    const float* x       = (const float*)d_in[0];
    const int*   mask    = (const int*)d_in[1];
    const float* w_off   = (const float*)d_in[2];
    const float* b_off   = (const float*)d_in[3];
    const float* conv_w  = (const float*)d_in[4];
    const float* conv_b  = (const float*)d_in[5];
    const float* gamma   = (const float*)d_in[6];
    const float* beta    = (const float*)d_in[7];
    const float* proj_w  = (const float*)d_in[8];
    const float* proj_b  = (const float*)d_in[9];
    float* out = (float*)d_out;

    cudaFuncSetAttribute(conv_mma_kernel,
                         cudaFuncAttributeMaxDynamicSharedMemorySize, SMEM_CONV);

    xconv_kernel<<<(int)(((size_t)BB*LL*WW/4 + 255) / 256), 256>>>(x);
    prep_b_kernel<<<(GG*CO*RDIM + 255) / 256, 256>>>(conv_w);
    offsets_kernel<<<BB * LL, 128>>>(x, w_off, b_off);
    dim3 cgrid(GG * 4, (BB * LL) / MT);   // (8, 128)
    conv_mma_kernel<<<cgrid, 512, SMEM_CONV>>>();
    ln_proj_kernel<<<BB * LL, 256>>>(conv_b, gamma, beta, proj_w, mask);
    final_kernel<<<BB, 256>>>(mask, proj_b, out);
}

// round 13
// speedup vs baseline: 3.9045x; 1.1293x over previous
#include <cuda_runtime.h>
#include <cuda_fp16.h>
#include <math.h>
#include <stdint.h>

#define BB 8
#define LL 2048
#define WW 1024
#define KK 5
#define GG 2
#define CI 512
#define CO 512
#define RDIM (KK*CI)        // 2560

// GEMM tiling
#define MT   64             // M per CTA
#define NTT  128            // N per CTA
#define KCB  32             // K-chunk (fp16 elems, 64B rows)
#define NCH  (RDIM/KCB)     // 80 chunks

// ---- static scratch ----
__device__ __half g_Bh[GG*CO*RDIM];           // [g][o][r] K-major fp16
__device__ __half g_xh[(size_t)BB*LL*WW];     // fp16 copy of x, 32 MB
__device__ int   g_p0[BB*LL*KK];
__device__ float g_frac[BB*LL*KK];
__device__ float g_h[(size_t)BB*LL*WW];       // conv output, 64 MB
__device__ float g_s[BB*LL];

// ============================================================
__device__ __forceinline__ uint32_t smem_u32(const void* p) {
    uint32_t a;
    asm("{ .reg .u64 t; cvta.to.shared.u64 t, %1; cvt.u32.u64 %0, t; }" : "=r"(a) : "l"(p));
    return a;
}
#define LDSM4(r, addr) \
    asm volatile("ldmatrix.sync.aligned.m8n8.x4.shared.b16 {%0,%1,%2,%3}, [%4];" \
        : "=r"((r)[0]), "=r"((r)[1]), "=r"((r)[2]), "=r"((r)[3]) : "r"(addr))
#define MMA16816(d, a, b0, b1) \
    asm volatile("mma.sync.aligned.m16n8k16.row.col.f32.f16.f16.f32 " \
        "{%0,%1,%2,%3}, {%4,%5,%6,%7}, {%8,%9}, {%0,%1,%2,%3};" \
        : "+f"((d)[0]), "+f"((d)[1]), "+f"((d)[2]), "+f"((d)[3]) \
        : "r"((a)[0]), "r"((a)[1]), "r"((a)[2]), "r"((a)[3]), "r"(b0), "r"(b1))

// ============================================================
// Kernel 0: x -> fp16 copy
// ============================================================
__global__ void xconv_kernel(const float* __restrict__ x) {
    size_t i = ((size_t)blockIdx.x * 256 + threadIdx.x) * 4;
    float4 v = *(const float4*)(x + i);
    __half2 h0 = __floats2half2_rn(v.x, v.y);
    __half2 h1 = __floats2half2_rn(v.z, v.w);
    *(uint2*)(g_xh + i) = make_uint2(*(uint32_t*)&h0, *(uint32_t*)&h1);
}

// ============================================================
// Kernel 1: B prep — conv_w [g][o][c][k] -> fp16 [g][o][r=k*CI+c]
// ============================================================
__global__ void prep_b_kernel(const float* __restrict__ conv_w) {
    int idx = blockIdx.x * 256 + threadIdx.x;
    if (idx >= GG*CO*RDIM) return;
    int r = idx % RDIM;
    int o = (idx / RDIM) % CO;
    int g = idx / (RDIM*CO);
    int k = r / CI, c = r % CI;
    float w = conv_w[(((g*CO + o)*CI + c)*KK) + k];
    g_Bh[idx] = __float2half_rn(w);
}

// ============================================================
// Kernel 2: offsets
// ============================================================
__global__ void offsets_kernel(const float* __restrict__ x,
                               const float* __restrict__ w_off,
                               const float* __restrict__ b_off) {
    int row = blockIdx.x;
    int tid = threadIdx.x;                // 128
    const float* xr = x + (size_t)row * WW;
    float acc[KK] = {0.f, 0.f, 0.f, 0.f, 0.f};
    for (int w = tid; w < WW; w += 128) {
        float xv = xr[w];
        #pragma unroll
        for (int k = 0; k < KK; k++) acc[k] += xv * w_off[w*KK + k];
    }
    __shared__ float sh[KK][128];
    #pragma unroll
    for (int k = 0; k < KK; k++) sh[k][tid] = acc[k];
    __syncthreads();
    for (int s = 64; s > 0; s >>= 1) {
        if (tid < s) {
            #pragma unroll
            for (int k = 0; k < KK; k++) sh[k][tid] += sh[k][tid + s];
        }
        __syncthreads();
    }
    if (tid < KK) {
        int k = tid;
        float off = tanhf(sh[k][0] + b_off[k]) * 2.0f;
        int l = row & (LL - 1);
        float pos = (float)l + ((float)k - 2.0f) + off;
        float p0 = floorf(pos);
        g_p0[row*KK + k]   = (int)p0;
        g_frac[row*KK + k] = pos - p0;
    }
}

// ============================================================
// Kernel 3: single-fp16 HMMA gathered GEMM (gathers from fp16 x)
// grid (GG*4, 256); 256 threads = 8 warps (2m x 4n), warp tile 32x32
// SMEM stage (12KB): A 4K | B 8K; 2 stages = 24KB -> 3 CTAs/SM
// rows are 64B (32 fp16); swizzle: grp16 ^= (row>>1)&3
// ============================================================
#define SA(s)   ((s)*12288 + 0)
#define SB(s)   ((s)*12288 + 4096)
#define SMEM_CONV (2*12288)

__global__ void __launch_bounds__(256, 3) conv_mma_kernel() {
    extern __shared__ __align__(128) char smem[];
    const uint32_t sb = smem_u32(smem);

    const int tid  = threadIdx.x;
    const int lane = tid & 31;
    const int wid  = tid >> 5;

    const int g      = blockIdx.x >> 2;
    const int n_base = (blockIdx.x & 3) * NTT;
    const int m_base = blockIdx.y * MT;

    // ---- loader mapping: thread t -> (row = t>>2 in 0..63, 8-col group = t&3) ----
    const int lrow = tid >> 2;
    const int lgrp = tid & 3;
    const int mg   = m_base + lrow;
    const __half* xb = g_xh + ((size_t)(mg >> 11)) * LL * WW + g * CI + lgrp * 8;
    const int*   p0p = &g_p0[mg * KK];
    const float* frp = &g_frac[mg * KK];
    // B: each thread loads rows lrow and lrow+64
    const size_t gBrow0 = (size_t)(g * CO + n_base + lrow) * RDIM + lgrp * 8;
    const size_t gBrow1 = gBrow0 + (size_t)64 * RDIM;
    const uint32_t swg  = (uint32_t)((lgrp ^ ((lrow >> 1) & 3)) << 4);
    const uint32_t offSTA  = (uint32_t)(lrow * 64) + swg;
    const uint32_t offSTB0 = (uint32_t)(lrow * 64) + swg;          // B row lrow
    const uint32_t offSTB1 = (uint32_t)((lrow + 64) * 64) + swg;   // B row lrow+64 (same swizzle: +64 rows preserves (row>>1)&3)

    // ---- compute mapping ----
    const int wm = (wid & 1) * 32;       // warp m offset (2 m-warps)
    const int wn = (wid >> 1) * 32;      // warp n offset (4 n-warps)
    const int rA0 = wm + (lane & 15), rA1 = rA0 + 16;
    const int rB0 = wn + (lane & 15), rB1 = rB0 + 16;
    const int sA0 = (rA0 >> 1) & 3, sA1 = (rA1 >> 1) & 3;
    const int sB0 = (rB0 >> 1) & 3, sB1 = (rB1 >> 1) & 3;
    const int hi16 = lane >> 4;          // 0/1 -> +16B within k

    float acc[2][4][4];
    #pragma unroll
    for (int mi = 0; mi < 2; mi++)
        #pragma unroll
        for (int nt = 0; nt < 4; nt++)
            #pragma unroll
            for (int e = 0; e < 4; e++) acc[mi][nt][e] = 0.f;

    // staging registers
    uint4 xv0, xv1, bhv0, bhv1;
    float lfrac;

    // ---- load chunk ch into staging regs ----
    auto LOADG = [&](int ch) {
        int ktap = ch >> 4;
        int c0   = (ch & 15) * KCB;
        int p0   = p0p[ktap];
        lfrac    = frp[ktap];
        int ok0 = (p0 >= 0) & (p0 < LL);
        int ok1 = (p0 >= -1) & (p0 < LL - 1);
        const __half* pa = xb + c0 + (size_t)p0 * WW;
        uint4 z = make_uint4(0u, 0u, 0u, 0u);
        xv0 = z; xv1 = z;
        if (ok0) xv0 = *(const uint4*)(pa);
        if (ok1) xv1 = *(const uint4*)(pa + WW);
        bhv0 = *(const uint4*)(g_Bh + gBrow0 + ch * KCB);
        bhv1 = *(const uint4*)(g_Bh + gBrow1 + ch * KCB);
    };

    // ---- convert staging regs and store to stage s ----
    auto STORES = [&](int s) {
        float w0 = 1.0f - lfrac, w1 = lfrac;
        const __half2* h0 = (const __half2*)&xv0;
        const __half2* h1 = (const __half2*)&xv1;
        __half2 hv[4];
        #pragma unroll
        for (int e = 0; e < 4; e++) {
            float2 f0 = __half22float2(h0[e]);
            float2 f1 = __half22float2(h1[e]);
            hv[e] = __floats2half2_rn(f0.x * w0 + f1.x * w1,
                                      f0.y * w0 + f1.y * w1);
        }
        *(uint4*)(smem + SA(s) + offSTA)  = *(uint4*)hv;
        *(uint4*)(smem + SB(s) + offSTB0) = bhv0;
        *(uint4*)(smem + SB(s) + offSTB1) = bhv1;
    };

    // ---- compute on stage s ----
    auto COMPUTE = [&](int s) {
        const uint32_t bAs = sb + SA(s), bBs = sb + SB(s);
        #pragma unroll
        for (int ks = 0; ks < 2; ks++) {
            const int grp = ks * 2 + hi16;
            const uint32_t oA0 = (uint32_t)(rA0 * 64 + ((grp ^ sA0) << 4));
            const uint32_t oA1 = (uint32_t)(rA1 * 64 + ((grp ^ sA1) << 4));
            const uint32_t oB0 = (uint32_t)(rB0 * 64 + ((grp ^ sB0) << 4));
            const uint32_t oB1 = (uint32_t)(rB1 * 64 + ((grp ^ sB1) << 4));
            uint32_t ah0[4], ah1[4], bh0[4], bh1[4];
            LDSM4(ah0, bAs + oA0);  LDSM4(ah1, bAs + oA1);
            LDSM4(bh0, bBs + oB0);  LDSM4(bh1, bBs + oB1);
            MMA16816(acc[0][0], ah0, bh0[0], bh0[2]);
            MMA16816(acc[0][1], ah0, bh0[1], bh0[3]);
            MMA16816(acc[0][2], ah0, bh1[0], bh1[2]);
            MMA16816(acc[0][3], ah0, bh1[1], bh1[3]);
            MMA16816(acc[1][0], ah1, bh0[0], bh0[2]);
            MMA16816(acc[1][1], ah1, bh0[1], bh0[3]);
            MMA16816(acc[1][2], ah1, bh1[0], bh1[2]);
            MMA16816(acc[1][3], ah1, bh1[1], bh1[3]);
        }
    };

    // ---- pipeline ----
    LOADG(0);
    STORES(0);
    __syncthreads();
    int s = 0;
    for (int ch = 0; ch < NCH; ch++) {
        if (ch + 1 < NCH) LOADG(ch + 1);
        COMPUTE(s);
        if (ch + 1 < NCH) STORES(s ^ 1);
        __syncthreads();
        s ^= 1;
    }

    // ---- epilogue: write accum -> g_h ----
    const int gcol = g * CO + n_base + wn;
    const int r    = lane >> 2;
    const int c    = (lane & 3) * 2;
    #pragma unroll
    for (int mi = 0; mi < 2; mi++) {
        int m = m_base + wm + mi * 16 + r;
        #pragma unroll
        for (int nt = 0; nt < 4; nt++) {
            int n = gcol + nt * 8 + c;
            float2 v0 = make_float2(acc[mi][nt][0], acc[mi][nt][1]);
            float2 v1 = make_float2(acc[mi][nt][2], acc[mi][nt][3]);
            *(float2*)&g_h[(size_t)m * WW + n]       = v0;
            *(float2*)&g_h[(size_t)(m + 8) * WW + n] = v1;
        }
    }
}

// ============================================================
// Kernel 4: per-row LayerNorm + mask + projection dot
// ============================================================
__global__ void ln_proj_kernel(const float* __restrict__ conv_b,
                               const float* __restrict__ gamma,
                               const float* __restrict__ beta,
                               const float* __restrict__ proj_w,
                               const int* __restrict__ mask) {
    int row = blockIdx.x;
    int tid = threadIdx.x;   // 256
    const float* hr = &g_h[(size_t)row * WW];

    float v[4];
    float s = 0.f, ss = 0.f;
    #pragma unroll
    for (int i = 0; i < 4; i++) {
        int w = tid + i * 256;
        float hv = hr[w] + conv_b[w];
        v[i] = hv;
        s  += hv;
        ss += hv * hv;
    }
    __shared__ float shA[8], shB[8];
    __shared__ float mu_sh, rstd_sh;
    #pragma unroll
    for (int o = 16; o > 0; o >>= 1) {
        s  += __shfl_xor_sync(0xffffffff, s,  o);
        ss += __shfl_xor_sync(0xffffffff, ss, o);
    }
    int warp = tid >> 5, lane = tid & 31;
    if (lane == 0) { shA[warp] = s; shB[warp] = ss; }
    __syncthreads();
    if (tid == 0) {
        float S = 0.f, SS = 0.f;
        #pragma unroll
        for (int i = 0; i < 8; i++) { S += shA[i]; SS += shB[i]; }
        float mu = S / (float)WW;
        float var = SS / (float)WW - mu * mu;
        mu_sh = mu;
        rstd_sh = rsqrtf(var + 1e-5f);
    }
    __syncthreads();
    float mu = mu_sh, rstd = rstd_sh;

    float dot = 0.f;
    #pragma unroll
    for (int i = 0; i < 4; i++) {
        int w = tid + i * 256;
        dot += ((v[i] - mu) * rstd * gamma[w] + beta[w]) * proj_w[w];
    }
    #pragma unroll
    for (int o = 16; o > 0; o >>= 1)
        dot += __shfl_xor_sync(0xffffffff, dot, o);
    __syncthreads();
    if (lane == 0) shA[warp] = dot;
    __syncthreads();
    if (tid == 0) {
        float D = 0.f;
        #pragma unroll
        for (int i = 0; i < 8; i++) D += shA[i];
        g_s[row] = (mask[row] != 0) ? 0.f : D;
    }
}

// ============================================================
// Kernel 5: final masked mean over L + proj_b
// ============================================================
__global__ void final_kernel(const int* __restrict__ mask,
                             const float* __restrict__ proj_b,
                             float* __restrict__ out) {
    int b = blockIdx.x;
    int tid = threadIdx.x;  // 256
    float s = 0.f;
    int cnt = 0;
    for (int l = tid; l < LL; l += 256) {
        s += g_s[b * LL + l];
        cnt += (mask[b * LL + l] != 0) ? 0 : 1;
    }
    #pragma unroll
    for (int o = 16; o > 0; o >>= 1) {
        s   += __shfl_xor_sync(0xffffffff, s, o);
        cnt += __shfl_xor_sync(0xffffffff, cnt, o);
    }
    __shared__ float shS[8];
    __shared__ int   shC[8];
    int warp = tid >> 5, lane = tid & 31;
    if (lane == 0) { shS[warp] = s; shC[warp] = cnt; }
    __syncthreads();
    if (tid == 0) {
        float S = 0.f; int C = 0;
        #pragma unroll
        for (int i = 0; i < 8; i++) { S += shS[i]; C += shC[i]; }
        float len = fmaxf((float)C, 1.0f);
        out[b] = S / len + proj_b[0];
    }
}

// ============================================================
extern "C" void kernel_launch(void* const* d_in, const int* in_sizes, int n_in,
                              void* d_out, int out_size) {
    const float* x       = (const float*)d_in[0];
    const int*   mask    = (const int*)d_in[1];
    const float* w_off   = (const float*)d_in[2];
    const float* b_off   = (const float*)d_in[3];
    const float* conv_w  = (const float*)d_in[4];
    const float* conv_b  = (const float*)d_in[5];
    const float* gamma   = (const float*)d_in[6];
    const float* beta    = (const float*)d_in[7];
    const float* proj_w  = (const float*)d_in[8];
    const float* proj_b  = (const float*)d_in[9];
    float* out = (float*)d_out;

    cudaFuncSetAttribute(conv_mma_kernel,
                         cudaFuncAttributeMaxDynamicSharedMemorySize, SMEM_CONV);

    xconv_kernel<<<(int)(((size_t)BB*LL*WW/4 + 255) / 256), 256>>>(x);
    prep_b_kernel<<<(GG*CO*RDIM + 255) / 256, 256>>>(conv_w);
    offsets_kernel<<<BB * LL, 128>>>(x, w_off, b_off);
    dim3 cgrid(GG * 4, (BB * LL) / MT);   // (8, 256)
    conv_mma_kernel<<<cgrid, 256, SMEM_CONV>>>();
    ln_proj_kernel<<<BB * LL, 256>>>(conv_b, gamma, beta, proj_w, mask);
    final_kernel<<<BB, 256>>>(mask, proj_b, out);
}

// round 15
// speedup vs baseline: 4.8086x; 1.2316x over previous
#include <cuda_runtime.h>
#include <cuda_fp16.h>
#include <math.h>
#include <stdint.h>

#define BB 8
#define LL 2048
#define WW 1024
#define KK 5
#define GG 2
#define CI 512
#define CO 512
#define RDIM (KK*CI)        // 2560

// GEMM tiling
#define MT   64             // M per CTA
#define NTT  128            // N per CTA
#define KCB  32             // K-chunk (fp16 elems, 64B rows)
#define NCH  (RDIM/KCB)     // 80 chunks
#define NK16 (RDIM/16)      // 160 k16 steps
#define NB8  (CO/8)         // 64 n8 blocks per group

// ---- static scratch ----
__device__ uint2 g_Bf[GG*NB8*NK16*32];        // B in MMA fragment order, 5.2 MB
__device__ __half g_xh[(size_t)BB*LL*WW];     // fp16 copy of x, 32 MB
__device__ int   g_p0[BB*LL*KK];
__device__ float g_frac[BB*LL*KK];
__device__ float g_h[(size_t)BB*LL*WW];       // conv output, 64 MB
__device__ float g_s[BB*LL];

// ============================================================
__device__ __forceinline__ uint32_t smem_u32(const void* p) {
    uint32_t a;
    asm("{ .reg .u64 t; cvta.to.shared.u64 t, %1; cvt.u32.u64 %0, t; }" : "=r"(a) : "l"(p));
    return a;
}
#define LDSM4(r, addr) \
    asm volatile("ldmatrix.sync.aligned.m8n8.x4.shared.b16 {%0,%1,%2,%3}, [%4];" \
        : "=r"((r)[0]), "=r"((r)[1]), "=r"((r)[2]), "=r"((r)[3]) : "r"(addr))
#define MMA16816(d, a, b0, b1) \
    asm volatile("mma.sync.aligned.m16n8k16.row.col.f32.f16.f16.f32 " \
        "{%0,%1,%2,%3}, {%4,%5,%6,%7}, {%8,%9}, {%0,%1,%2,%3};" \
        : "+f"((d)[0]), "+f"((d)[1]), "+f"((d)[2]), "+f"((d)[3]) \
        : "r"((a)[0]), "r"((a)[1]), "r"((a)[2]), "r"((a)[3]), "r"(b0), "r"(b1))

// ============================================================
// Kernel 0: x -> fp16 copy
// ============================================================
__global__ void xconv_kernel(const float* __restrict__ x) {
    size_t i = ((size_t)blockIdx.x * 256 + threadIdx.x) * 4;
    float4 v = *(const float4*)(x + i);
    __half2 h0 = __floats2half2_rn(v.x, v.y);
    __half2 h1 = __floats2half2_rn(v.z, v.w);
    *(uint2*)(g_xh + i) = make_uint2(*(uint32_t*)&h0, *(uint32_t*)&h1);
}

// ============================================================
// Kernel 1: B prep — conv_w [g][o][c][k] -> fragment-order fp16
// block index: ((g*NB8 + nb)*NK16 + ko)*32 + lane
// lane holds b0 = {B[n][k], B[n][k+1]}, b1 = {B[n][k+8], B[n][k+9]}
//   where n = nb*8 + lane/4, k = ko*16 + (lane%4)*2, r = k (k*CI+c order)
// ============================================================
__global__ void prep_b_kernel(const float* __restrict__ conv_w) {
    int idx = blockIdx.x * 256 + threadIdx.x;
    if (idx >= GG*NB8*NK16*32) return;
    int lane = idx & 31;
    int ko   = (idx >> 5) % NK16;
    int nb   = (idx >> 5) / NK16 % NB8;
    int g    = idx / (32*NK16*NB8);
    int n = nb*8 + (lane >> 2);          // out channel within group
    int r = ko*16 + (lane & 3)*2;        // reduction index = ktap*CI + c
    const float* wbase = conv_w + ((size_t)(g*CO + n))*CI*KK;
    float w0, w1, w2, w3;
    {
        int ktap = r / CI,        c = r % CI;
        w0 = wbase[c*KK + ktap];
        w1 = wbase[(c+1)*KK + ktap];
        int r8 = r + 8;
        int ktap8 = r8 / CI,      c8 = r8 % CI;
        w2 = wbase[c8*KK + ktap8];
        w3 = wbase[(c8+1)*KK + ktap8];
    }
    __half2 b0 = __floats2half2_rn(w0, w1);
    __half2 b1 = __floats2half2_rn(w2, w3);
    g_Bf[idx] = make_uint2(*(uint32_t*)&b0, *(uint32_t*)&b1);
}

// ============================================================
// Kernel 2: offsets
// ============================================================
__global__ void offsets_kernel(const float* __restrict__ x,
                               const float* __restrict__ w_off,
                               const float* __restrict__ b_off) {
    int row = blockIdx.x;
    int tid = threadIdx.x;                // 128
    const float* xr = x + (size_t)row * WW;
    float acc[KK] = {0.f, 0.f, 0.f, 0.f, 0.f};
    for (int w = tid; w < WW; w += 128) {
        float xv = xr[w];
        #pragma unroll
        for (int k = 0; k < KK; k++) acc[k] += xv * w_off[w*KK + k];
    }
    __shared__ float sh[KK][128];
    #pragma unroll
    for (int k = 0; k < KK; k++) sh[k][tid] = acc[k];
    __syncthreads();
    for (int s = 64; s > 0; s >>= 1) {
        if (tid < s) {
            #pragma unroll
            for (int k = 0; k < KK; k++) sh[k][tid] += sh[k][tid + s];
        }
        __syncthreads();
    }
    if (tid < KK) {
        int k = tid;
        float off = tanhf(sh[k][0] + b_off[k]) * 2.0f;
        int l = row & (LL - 1);
        float pos = (float)l + ((float)k - 2.0f) + off;
        float p0 = floorf(pos);
        g_p0[row*KK + k]   = (int)p0;
        g_frac[row*KK + k] = pos - p0;
    }
}

// ============================================================
// Kernel 3: fp16 HMMA gathered GEMM; A via SMEM, B via fragment LDG
// grid (GG*4, 256); 256 threads = 8 warps (2m x 4n), warp tile 32x32
// SMEM stage (4KB): A only; 2 stages = 8KB
// ============================================================
#define SA(s)   ((s)*4096)
#define SMEM_CONV (2*4096)

__global__ void __launch_bounds__(256, 3) conv_mma_kernel() {
    extern __shared__ __align__(128) char smem[];
    const uint32_t sb = smem_u32(smem);

    const int tid  = threadIdx.x;
    const int lane = tid & 31;
    const int wid  = tid >> 5;

    const int g      = blockIdx.x >> 2;
    const int n_base = (blockIdx.x & 3) * NTT;
    const int m_base = blockIdx.y * MT;

    // ---- A loader mapping: thread t -> (row = t>>2 in 0..63, 8-col group = t&3) ----
    const int lrow = tid >> 2;
    const int lgrp = tid & 3;
    const int mg   = m_base + lrow;
    const __half* xb = g_xh + ((size_t)(mg >> 11)) * LL * WW + g * CI + lgrp * 8;
    const int*   p0p = &g_p0[mg * KK];
    const float* frp = &g_frac[mg * KK];
    const uint32_t offSTA = (uint32_t)(lrow * 64 + ((lgrp ^ ((lrow >> 1) & 3)) << 4));

    // ---- compute mapping ----
    const int wm = (wid & 1) * 32;       // warp m offset (2 m-warps)
    const int wn = (wid >> 1) * 32;      // warp n offset (4 n-warps)
    const int rA0 = wm + (lane & 15), rA1 = rA0 + 16;
    const int sA0 = (rA0 >> 1) & 3, sA1 = (rA1 >> 1) & 3;
    const int hi16 = lane >> 4;
    // hoisted LDSM offsets for ks=0,1
    uint32_t oA0k[2], oA1k[2];
    #pragma unroll
    for (int ks = 0; ks < 2; ks++) {
        int grp = ks * 2 + hi16;
        oA0k[ks] = (uint32_t)(rA0 * 64 + ((grp ^ sA0) << 4));
        oA1k[ks] = (uint32_t)(rA1 * 64 + ((grp ^ sA1) << 4));
    }

    // B fragment base for this warp: n8 block nb0 = (n_base + wn)/8
    const uint2* BfBase = g_Bf + ((size_t)(g*NB8 + ((n_base + wn) >> 3)) * NK16) * 32 + lane;

    float acc[2][4][4];
    #pragma unroll
    for (int mi = 0; mi < 2; mi++)
        #pragma unroll
        for (int nt = 0; nt < 4; nt++)
            #pragma unroll
            for (int e = 0; e < 4; e++) acc[mi][nt][e] = 0.f;

    // staging registers
    uint4 xv0, xv1;
    float lfrac;
    uint2 bfr[8];                        // B fragments for current chunk [ks*4 + b4]

    // ---- A global load for chunk ch ----
    auto LOADA = [&](int ch) {
        int ktap = ch >> 4;
        int c0   = (ch & 15) * KCB;
        int p0   = p0p[ktap];
        lfrac    = frp[ktap];
        int ok0 = (p0 >= 0) & (p0 < LL);
        int ok1 = (p0 >= -1) & (p0 < LL - 1);
        const __half* pa = xb + c0 + (size_t)p0 * WW;
        uint4 z = make_uint4(0u, 0u, 0u, 0u);
        xv0 = z; xv1 = z;
        if (ok0) xv0 = *(const uint4*)(pa);
        if (ok1) xv1 = *(const uint4*)(pa + WW);
    };

    // ---- B fragment loads for chunk ch ----
    auto LOADB = [&](int ch) {
        #pragma unroll
        for (int ks = 0; ks < 2; ks++)
            #pragma unroll
            for (int b4 = 0; b4 < 4; b4++)
                bfr[ks*4 + b4] = BfBase[((size_t)b4 * NK16 + (ch*2 + ks)) * 32];
    };

    // ---- convert A staging and store to stage s ----
    auto STORESA = [&](int s) {
        float w0 = 1.0f - lfrac, w1 = lfrac;
        const __half2* h0 = (const __half2*)&xv0;
        const __half2* h1 = (const __half2*)&xv1;
        __half2 hv[4];
        #pragma unroll
        for (int e = 0; e < 4; e++) {
            float2 f0 = __half22float2(h0[e]);
            float2 f1 = __half22float2(h1[e]);
            hv[e] = __floats2half2_rn(f0.x * w0 + f1.x * w1,
                                      f0.y * w0 + f1.y * w1);
        }
        *(uint4*)(smem + SA(s) + offSTA) = *(uint4*)hv;
    };

    // ---- compute on stage s (A from smem, B from bfr regs) ----
    auto COMPUTE = [&](int s) {
        const uint32_t bAs = sb + SA(s);
        #pragma unroll
        for (int ks = 0; ks < 2; ks++) {
            uint32_t ah0[4], ah1[4];
            LDSM4(ah0, bAs + oA0k[ks]);
            LDSM4(ah1, bAs + oA1k[ks]);
            #pragma unroll
            for (int b4 = 0; b4 < 4; b4++) {
                uint2 b = bfr[ks*4 + b4];
                MMA16816(acc[0][b4], ah0, b.x, b.y);
                MMA16816(acc[1][b4], ah1, b.x, b.y);
            }
        }
    };

    // ---- pipeline ----
    LOADB(0);
    LOADA(0);
    STORESA(0);
    __syncthreads();
    int s = 0;
    for (int ch = 0; ch < NCH; ch++) {
        if (ch + 1 < NCH) LOADA(ch + 1);
        COMPUTE(s);
        if (ch + 1 < NCH) {
            LOADB(ch + 1);
            STORESA(s ^ 1);
        }
        __syncthreads();
        s ^= 1;
    }

    // ---- epilogue: write accum -> g_h ----
    const int gcol = g * CO + n_base + wn;
    const int r    = lane >> 2;
    const int c    = (lane & 3) * 2;
    #pragma unroll
    for (int mi = 0; mi < 2; mi++) {
        int m = m_base + wm + mi * 16 + r;
        #pragma unroll
        for (int nt = 0; nt < 4; nt++) {
            int n = gcol + nt * 8 + c;
            float2 v0 = make_float2(acc[mi][nt][0], acc[mi][nt][1]);
            float2 v1 = make_float2(acc[mi][nt][2], acc[mi][nt][3]);
            *(float2*)&g_h[(size_t)m * WW + n]       = v0;
            *(float2*)&g_h[(size_t)(m + 8) * WW + n] = v1;
        }
    }
}

// ============================================================
// Kernel 4: per-row LayerNorm + mask + projection dot
// ============================================================
__global__ void ln_proj_kernel(const float* __restrict__ conv_b,
                               const float* __restrict__ gamma,
                               const float* __restrict__ beta,
                               const float* __restrict__ proj_w,
                               const int* __restrict__ mask) {
    int row = blockIdx.x;
    int tid = threadIdx.x;   // 256
    const float* hr = &g_h[(size_t)row * WW];

    float v[4];
    float s = 0.f, ss = 0.f;
    #pragma unroll
    for (int i = 0; i < 4; i++) {
        int w = tid + i * 256;
        float hv = hr[w] + conv_b[w];
        v[i] = hv;
        s  += hv;
        ss += hv * hv;
    }
    __shared__ float shA[8], shB[8];
    __shared__ float mu_sh, rstd_sh;
    #pragma unroll
    for (int o = 16; o > 0; o >>= 1) {
        s  += __shfl_xor_sync(0xffffffff, s,  o);
        ss += __shfl_xor_sync(0xffffffff, ss, o);
    }
    int warp = tid >> 5, lane = tid & 31;
    if (lane == 0) { shA[warp] = s; shB[warp] = ss; }
    __syncthreads();
    if (tid == 0) {
        float S = 0.f, SS = 0.f;
        #pragma unroll
        for (int i = 0; i < 8; i++) { S += shA[i]; SS += shB[i]; }
        float mu = S / (float)WW;
        float var = SS / (float)WW - mu * mu;
        mu_sh = mu;
        rstd_sh = rsqrtf(var + 1e-5f);
    }
    __syncthreads();
    float mu = mu_sh, rstd = rstd_sh;

    float dot = 0.f;
    #pragma unroll
    for (int i = 0; i < 4; i++) {
        int w = tid + i * 256;
        dot += ((v[i] - mu) * rstd * gamma[w] + beta[w]) * proj_w[w];
    }
    #pragma unroll
    for (int o = 16; o > 0; o >>= 1)
        dot += __shfl_xor_sync(0xffffffff, dot, o);
    __syncthreads();
    if (lane == 0) shA[warp] = dot;
    __syncthreads();
    if (tid == 0) {
        float D = 0.f;
        #pragma unroll
        for (int i = 0; i < 8; i++) D += shA[i];
        g_s[row] = (mask[row] != 0) ? 0.f : D;
    }
}

// ============================================================
// Kernel 5: final masked mean over L + proj_b
// ============================================================
__global__ void final_kernel(const int* __restrict__ mask,
                             const float* __restrict__ proj_b,
                             float* __restrict__ out) {
    int b = blockIdx.x;
    int tid = threadIdx.x;  // 256
    float s = 0.f;
    int cnt = 0;
    for (int l = tid; l < LL; l += 256) {
        s += g_s[b * LL + l];
        cnt += (mask[b * LL + l] != 0) ? 0 : 1;
    }
    #pragma unroll
    for (int o = 16; o > 0; o >>= 1) {
        s   += __shfl_xor_sync(0xffffffff, s, o);
        cnt += __shfl_xor_sync(0xffffffff, cnt, o);
    }
    __shared__ float shS[8];
    __shared__ int   shC[8];
    int warp = tid >> 5, lane = tid & 31;
    if (lane == 0) { shS[warp] = s; shC[warp] = cnt; }
    __syncthreads();
    if (tid == 0) {
        float S = 0.f; int C = 0;
        #pragma unroll
        for (int i = 0; i < 8; i++) { S += shS[i]; C += shC[i]; }
        float len = fmaxf((float)C, 1.0f);
        out[b] = S / len + proj_b[0];
    }
}

// ============================================================
extern "C" void kernel_launch(void* const* d_in, const int* in_sizes, int n_in,
                              void* d_out, int out_size) {
    const float* x       = (const float*)d_in[0];
    const int*   mask    = (const int*)d_in[1];
    const float* w_off   = (const float*)d_in[2];
    const float* b_off   = (const float*)d_in[3];
    const float* conv_w  = (const float*)d_in[4];
    const float* conv_b  = (const float*)d_in[5];
    const float* gamma   = (const float*)d_in[6];
    const float* beta    = (const float*)d_in[7];
    const float* proj_w  = (const float*)d_in[8];
    const float* proj_b  = (const float*)d_in[9];
    float* out = (float*)d_out;

    cudaFuncSetAttribute(conv_mma_kernel,
                         cudaFuncAttributeMaxDynamicSharedMemorySize, SMEM_CONV);

    xconv_kernel<<<(int)(((size_t)BB*LL*WW/4 + 255) / 256), 256>>>(x);
    prep_b_kernel<<<(GG*NB8*NK16*32 + 255) / 256, 256>>>(conv_w);
    offsets_kernel<<<BB * LL, 128>>>(x, w_off, b_off);
    dim3 cgrid(GG * 4, (BB * LL) / MT);   // (8, 256)
    conv_mma_kernel<<<cgrid, 256, SMEM_CONV>>>();
    ln_proj_kernel<<<BB * LL, 256>>>(conv_b, gamma, beta, proj_w, mask);
    final_kernel<<<BB, 256>>>(mask, proj_b, out);
}

// round 16
// speedup vs baseline: 5.1181x; 1.0644x over previous
#include <cuda_runtime.h>
#include <cuda_fp16.h>
#include <math.h>
#include <stdint.h>

#define BB 8
#define LL 2048
#define WW 1024
#define KK 5
#define GG 2
#define CI 512
#define CO 512
#define RDIM (KK*CI)        // 2560

// GEMM tiling
#define MT   64             // M per CTA
#define NTT  128            // N per CTA
#define KCB  32             // K-chunk (fp16 elems)
#define NCH  (RDIM/KCB)     // 80 chunks
#define NQ   16             // n32 quads per group (512/32)

// ---- static scratch ----
// B fragments: [g][nbq][ch][b4][lane] uint4 = {b0_ks0, b1_ks0, b0_ks1, b1_ks1}
__device__ uint4 g_Bf4[GG*NQ*NCH*4*32];       // 5.2 MB
__device__ __half g_xh[(size_t)BB*LL*WW];     // fp16 copy of x, 32 MB
__device__ int   g_p0[BB*LL*KK];
__device__ float g_frac[BB*LL*KK];
__device__ float g_h[(size_t)BB*LL*WW];       // conv output, 64 MB
__device__ float g_s[BB*LL];

// ============================================================
__device__ __forceinline__ uint32_t smem_u32(const void* p) {
    uint32_t a;
    asm("{ .reg .u64 t; cvta.to.shared.u64 t, %1; cvt.u32.u64 %0, t; }" : "=r"(a) : "l"(p));
    return a;
}
#define LDSM4(r, addr) \
    asm volatile("ldmatrix.sync.aligned.m8n8.x4.shared.b16 {%0,%1,%2,%3}, [%4];" \
        : "=r"((r)[0]), "=r"((r)[1]), "=r"((r)[2]), "=r"((r)[3]) : "r"(addr))
#define MMA16816(d, a, b0, b1) \
    asm volatile("mma.sync.aligned.m16n8k16.row.col.f32.f16.f16.f32 " \
        "{%0,%1,%2,%3}, {%4,%5,%6,%7}, {%8,%9}, {%0,%1,%2,%3};" \
        : "+f"((d)[0]), "+f"((d)[1]), "+f"((d)[2]), "+f"((d)[3]) \
        : "r"((a)[0]), "r"((a)[1]), "r"((a)[2]), "r"((a)[3]), "r"(b0), "r"(b1))

// ============================================================
// Kernel 1: B prep — conv_w [g][o][c][k] -> packed fragment order
// ============================================================
__global__ void prep_b_kernel(const float* __restrict__ conv_w) {
    int idx = blockIdx.x * 256 + threadIdx.x;
    if (idx >= GG*NQ*NCH*4*32) return;
    int lane = idx & 31;
    int nbl  = (idx >> 5) & 3;
    int ch   = (idx >> 7) % NCH;
    int nbq  = ((idx >> 7) / NCH) % NQ;
    int g    = idx / (32*4*NCH*NQ);
    int n = (nbq*4 + nbl)*8 + (lane >> 2);   // out channel within group
    const float* wb = conv_w + ((size_t)(g*CO + n))*CI*KK;
    uint32_t packed[4];
    #pragma unroll
    for (int ks = 0; ks < 2; ks++) {
        int r = (ch*2 + ks)*16 + (lane & 3)*2;   // reduction index = ktap*CI + c
        float v0 = wb[(r       % CI)*KK + (r       / CI)];
        float v1 = wb[((r+1)   % CI)*KK + ((r+1)   / CI)];
        float v2 = wb[((r+8)   % CI)*KK + ((r+8)   / CI)];
        float v3 = wb[((r+9)   % CI)*KK + ((r+9)   / CI)];
        __half2 b0 = __floats2half2_rn(v0, v1);
        __half2 b1 = __floats2half2_rn(v2, v3);
        packed[ks*2+0] = *(uint32_t*)&b0;
        packed[ks*2+1] = *(uint32_t*)&b1;
    }
    g_Bf4[idx] = make_uint4(packed[0], packed[1], packed[2], packed[3]);
}

// ============================================================
// Kernel 2: offsets + x->fp16 conversion (fused)
// ============================================================
__global__ void offsets_kernel(const float* __restrict__ x,
                               const float* __restrict__ w_off,
                               const float* __restrict__ b_off) {
    int row = blockIdx.x;
    int tid = threadIdx.x;                // 128
    const float* xr = x + (size_t)row * WW;
    __half* xhr = g_xh + (size_t)row * WW;
    float acc[KK] = {0.f, 0.f, 0.f, 0.f, 0.f};
    for (int w = tid; w < WW; w += 128) {
        float xv = xr[w];
        xhr[w] = __float2half_rn(xv);
        #pragma unroll
        for (int k = 0; k < KK; k++) acc[k] += xv * w_off[w*KK + k];
    }
    __shared__ float sh[KK][128];
    #pragma unroll
    for (int k = 0; k < KK; k++) sh[k][tid] = acc[k];
    __syncthreads();
    for (int s = 64; s > 0; s >>= 1) {
        if (tid < s) {
            #pragma unroll
            for (int k = 0; k < KK; k++) sh[k][tid] += sh[k][tid + s];
        }
        __syncthreads();
    }
    if (tid < KK) {
        int k = tid;
        float off = tanhf(sh[k][0] + b_off[k]) * 2.0f;
        int l = row & (LL - 1);
        float pos = (float)l + ((float)k - 2.0f) + off;
        float p0 = floorf(pos);
        g_p0[row*KK + k]   = (int)p0;
        g_frac[row*KK + k] = pos - p0;
    }
}

// ============================================================
// Kernel 3: fp16 HMMA gathered GEMM; A via SMEM, B via packed fragment LDG
// grid (GG*4, 256); 256 threads = 8 warps (2m x 4n), warp tile 32x32
// SMEM stage (4KB): A only; 2 stages = 8KB
// ============================================================
#define SA(s)   ((s)*4096)
#define SMEM_CONV (2*4096)

__global__ void __launch_bounds__(256, 3) conv_mma_kernel() {
    extern __shared__ __align__(128) char smem[];
    const uint32_t sb = smem_u32(smem);

    const int tid  = threadIdx.x;
    const int lane = tid & 31;
    const int wid  = tid >> 5;

    const int g      = blockIdx.x >> 2;
    const int n_base = (blockIdx.x & 3) * NTT;
    const int m_base = blockIdx.y * MT;

    // ---- A loader mapping ----
    const int lrow = tid >> 2;
    const int lgrp = tid & 3;
    const int mg   = m_base + lrow;
    const __half* xb = g_xh + ((size_t)(mg >> 11)) * LL * WW + g * CI + lgrp * 8;
    const int*   p0p = &g_p0[mg * KK];
    const float* frp = &g_frac[mg * KK];
    const uint32_t offSTA = (uint32_t)(lrow * 64 + ((lgrp ^ ((lrow >> 1) & 3)) << 4));

    // ---- compute mapping ----
    const int wm = (wid & 1) * 32;
    const int wn = (wid >> 1) * 32;
    const int rA0 = wm + (lane & 15), rA1 = rA0 + 16;
    const int sA0 = (rA0 >> 1) & 3, sA1 = (rA1 >> 1) & 3;
    const int hi16 = lane >> 4;
    uint32_t oA0k[2], oA1k[2];
    #pragma unroll
    for (int ks = 0; ks < 2; ks++) {
        int grp = ks * 2 + hi16;
        oA0k[ks] = (uint32_t)(rA0 * 64 + ((grp ^ sA0) << 4));
        oA1k[ks] = (uint32_t)(rA1 * 64 + ((grp ^ sA1) << 4));
    }

    // B fragment pointer: warp's quad = (n_base+wn)>>5; 4 frags contiguous per chunk
    const uint4* bp = g_Bf4 + ((size_t)(g*NQ + ((n_base + wn) >> 5)) * NCH) * 4 * 32 + lane;

    float acc[2][4][4];
    #pragma unroll
    for (int mi = 0; mi < 2; mi++)
        #pragma unroll
        for (int nt = 0; nt < 4; nt++)
            #pragma unroll
            for (int e = 0; e < 4; e++) acc[mi][nt][e] = 0.f;

    // staging registers
    uint4 xv0, xv1;
    float lfrac;
    uint4 bfr[4];

    auto LOADA = [&](int ch) {
        int ktap = ch >> 4;
        int c0   = (ch & 15) * KCB;
        int p0   = p0p[ktap];
        lfrac    = frp[ktap];
        int ok0 = (p0 >= 0) & (p0 < LL);
        int ok1 = (p0 >= -1) & (p0 < LL - 1);
        const __half* pa = xb + c0 + (size_t)p0 * WW;
        uint4 z = make_uint4(0u, 0u, 0u, 0u);
        xv0 = z; xv1 = z;
        if (ok0) xv0 = *(const uint4*)(pa);
        if (ok1) xv1 = *(const uint4*)(pa + WW);
    };

    auto LOADB = [&]() {
        bfr[0] = bp[0];
        bfr[1] = bp[32];
        bfr[2] = bp[64];
        bfr[3] = bp[96];
        bp += 128;
    };

    auto STORESA = [&](int s) {
        float w0 = 1.0f - lfrac, w1 = lfrac;
        const __half2* h0 = (const __half2*)&xv0;
        const __half2* h1 = (const __half2*)&xv1;
        __half2 hv[4];
        #pragma unroll
        for (int e = 0; e < 4; e++) {
            float2 f0 = __half22float2(h0[e]);
            float2 f1 = __half22float2(h1[e]);
            hv[e] = __floats2half2_rn(f0.x * w0 + f1.x * w1,
                                      f0.y * w0 + f1.y * w1);
        }
        *(uint4*)(smem + SA(s) + offSTA) = *(uint4*)hv;
    };

    auto COMPUTE = [&](int s) {
        const uint32_t bAs = sb + SA(s);
        // ks = 0
        {
            uint32_t ah0[4], ah1[4];
            LDSM4(ah0, bAs + oA0k[0]);
            LDSM4(ah1, bAs + oA1k[0]);
            #pragma unroll
            for (int b4 = 0; b4 < 4; b4++) {
                MMA16816(acc[0][b4], ah0, bfr[b4].x, bfr[b4].y);
                MMA16816(acc[1][b4], ah1, bfr[b4].x, bfr[b4].y);
            }
        }
        // ks = 1
        {
            uint32_t ah0[4], ah1[4];
            LDSM4(ah0, bAs + oA0k[1]);
            LDSM4(ah1, bAs + oA1k[1]);
            #pragma unroll
            for (int b4 = 0; b4 < 4; b4++) {
                MMA16816(acc[0][b4], ah0, bfr[b4].z, bfr[b4].w);
                MMA16816(acc[1][b4], ah1, bfr[b4].z, bfr[b4].w);
            }
        }
    };

    // ---- pipeline (unrolled x2, compile-time stages) ----
    LOADB();            // chunk 0
    LOADA(0);
    STORESA(0);
    __syncthreads();
    for (int ch = 0; ch < NCH; ch += 2) {
        // chunk ch (stage 0), bfr holds ch
        LOADA(ch + 1);
        COMPUTE(0);
        LOADB();        // bfr <- ch+1
        STORESA(1);
        __syncthreads();
        // chunk ch+1 (stage 1), bfr holds ch+1
        bool more = (ch + 2 < NCH);
        if (more) LOADA(ch + 2);
        COMPUTE(1);
        if (more) {
            LOADB();    // bfr <- ch+2
            STORESA(0);
        }
        __syncthreads();
    }

    // ---- epilogue: write accum -> g_h ----
    const int gcol = g * CO + n_base + wn;
    const int r    = lane >> 2;
    const int c    = (lane & 3) * 2;
    #pragma unroll
    for (int mi = 0; mi < 2; mi++) {
        int m = m_base + wm + mi * 16 + r;
        #pragma unroll
        for (int nt = 0; nt < 4; nt++) {
            int n = gcol + nt * 8 + c;
            float2 v0 = make_float2(acc[mi][nt][0], acc[mi][nt][1]);
            float2 v1 = make_float2(acc[mi][nt][2], acc[mi][nt][3]);
            *(float2*)&g_h[(size_t)m * WW + n]       = v0;
            *(float2*)&g_h[(size_t)(m + 8) * WW + n] = v1;
        }
    }
}

// ============================================================
// Kernel 4: per-row LayerNorm + mask + projection dot
// ============================================================
__global__ void ln_proj_kernel(const float* __restrict__ conv_b,
                               const float* __restrict__ gamma,
                               const float* __restrict__ beta,
                               const float* __restrict__ proj_w,
                               const int* __restrict__ mask) {
    int row = blockIdx.x;
    int tid = threadIdx.x;   // 256
    const float* hr = &g_h[(size_t)row * WW];

    float v[4];
    float s = 0.f, ss = 0.f;
    #pragma unroll
    for (int i = 0; i < 4; i++) {
        int w = tid + i * 256;
        float hv = hr[w] + conv_b[w];
        v[i] = hv;
        s  += hv;
        ss += hv * hv;
    }
    __shared__ float shA[8], shB[8];
    __shared__ float mu_sh, rstd_sh;
    #pragma unroll
    for (int o = 16; o > 0; o >>= 1) {
        s  += __shfl_xor_sync(0xffffffff, s,  o);
        ss += __shfl_xor_sync(0xffffffff, ss, o);
    }
    int warp = tid >> 5, lane = tid & 31;
    if (lane == 0) { shA[warp] = s; shB[warp] = ss; }
    __syncthreads();
    if (tid == 0) {
        float S = 0.f, SS = 0.f;
        #pragma unroll
        for (int i = 0; i < 8; i++) { S += shA[i]; SS += shB[i]; }
        float mu = S / (float)WW;
        float var = SS / (float)WW - mu * mu;
        mu_sh = mu;
        rstd_sh = rsqrtf(var + 1e-5f);
    }
    __syncthreads();
    float mu = mu_sh, rstd = rstd_sh;

    float dot = 0.f;
    #pragma unroll
    for (int i = 0; i < 4; i++) {
        int w = tid + i * 256;
        dot += ((v[i] - mu) * rstd * gamma[w] + beta[w]) * proj_w[w];
    }
    #pragma unroll
    for (int o = 16; o > 0; o >>= 1)
        dot += __shfl_xor_sync(0xffffffff, dot, o);
    __syncthreads();
    if (lane == 0) shA[warp] = dot;
    __syncthreads();
    if (tid == 0) {
        float D = 0.f;
        #pragma unroll
        for (int i = 0; i < 8; i++) D += shA[i];
        g_s[row] = (mask[row] != 0) ? 0.f : D;
    }
}

// ============================================================
// Kernel 5: final masked mean over L + proj_b
// ============================================================
__global__ void final_kernel(const int* __restrict__ mask,
                             const float* __restrict__ proj_b,
                             float* __restrict__ out) {
    int b = blockIdx.x;
    int tid = threadIdx.x;  // 256
    float s = 0.f;
    int cnt = 0;
    for (int l = tid; l < LL; l += 256) {
        s += g_s[b * LL + l];
        cnt += (mask[b * LL + l] != 0) ? 0 : 1;
    }
    #pragma unroll
    for (int o = 16; o > 0; o >>= 1) {
        s   += __shfl_xor_sync(0xffffffff, s, o);
        cnt += __shfl_xor_sync(0xffffffff, cnt, o);
    }
    __shared__ float shS[8];
    __shared__ int   shC[8];
    int warp = tid >> 5, lane = tid & 31;
    if (lane == 0) { shS[warp] = s; shC[warp] = cnt; }
    __syncthreads();
    if (tid == 0) {
        float S = 0.f; int C = 0;
        #pragma unroll
        for (int i = 0; i < 8; i++) { S += shS[i]; C += shC[i]; }
        float len = fmaxf((float)C, 1.0f);
        out[b] = S / len + proj_b[0];
    }
}

// ============================================================
extern "C" void kernel_launch(void* const* d_in, const int* in_sizes, int n_in,
                              void* d_out, int out_size) {
    const float* x       = (const float*)d_in[0];
    const int*   mask    = (const int*)d_in[1];
    const float* w_off   = (const float*)d_in[2];
    const float* b_off   = (const float*)d_in[3];
    const float* conv_w  = (const float*)d_in[4];
    const float* conv_b  = (const float*)d_in[5];
    const float* gamma   = (const float*)d_in[6];
    const float* beta    = (const float*)d_in[7];
    const float* proj_w  = (const float*)d_in[8];
    const float* proj_b  = (const float*)d_in[9];
    float* out = (float*)d_out;

    cudaFuncSetAttribute(conv_mma_kernel,
                         cudaFuncAttributeMaxDynamicSharedMemorySize, SMEM_CONV);

    prep_b_kernel<<<(GG*NQ*NCH*4*32 + 255) / 256, 256>>>(conv_w);
    offsets_kernel<<<BB * LL, 128>>>(x, w_off, b_off);
    dim3 cgrid(GG * 4, (BB * LL) / MT);   // (8, 256)
    conv_mma_kernel<<<cgrid, 256, SMEM_CONV>>>();
    ln_proj_kernel<<<BB * LL, 256>>>(conv_b, gamma, beta, proj_w, mask);
    final_kernel<<<BB, 256>>>(mask, proj_b, out);
}